// round 5
// baseline (speedup 1.0000x reference)
#include <cuda_runtime.h>
#include <cuda_fp16.h>
#include <cstdint>

#define N_MAX 100000
#define CIN   64
#define CMID  64
#define COUT  128
#define BN_EPS 1e-5
#define NSLOT 16

// ---------------- packed fp32x2 helpers (sm_103a) ----------------
#define FFMA2(d, a, b) \
    asm("fma.rn.f32x2 %0, %1, %2, %0;" : "+l"(d) : "l"(a), "l"(b))
#define DUP2(d, s) \
    asm("mov.b64 %0, {%1, %1};" : "=l"(d) : "f"(s))
#define UNPK2(lo, hi, p) \
    asm("mov.b64 {%0, %1}, %2;" : "=f"(lo), "=f"(hi) : "l"(p))

union F4U { float4 f; unsigned long long u[2]; };

// ---------------- device scratch (static: no allocations allowed) ----------------
__device__ int    g_count[N_MAX];
__device__ float  g_T1[(size_t)N_MAX * CMID];    // feat @ W1 + b1 (25.6 MB)
__device__ __half g_T2h[(size_t)N_MAX * COUT];   // T2 pre-BN2, fp16 (25.6 MB)
__device__ double g_sum1[NSLOT * CMID], g_sq1[NSLOT * CMID];
__device__ double g_sum2[NSLOT * COUT], g_sq2[NSLOT * COUT];
__device__ float  g_s1[CMID], g_t1[CMID];
__device__ float  g_s2[COUT], g_t2[COUT];
__device__ int    g_is64;

// ---------------- K0: zero counters + accumulators ----------------
__global__ void k_zero(int n) {
    int i  = blockIdx.x * blockDim.x + threadIdx.x;
    int st = gridDim.x * blockDim.x;
    for (int j = i; j < n; j += st) g_count[j] = 0;
    if (i < NSLOT * CMID) { g_sum1[i] = 0.0; g_sq1[i] = 0.0; }
    if (i < NSLOT * COUT) { g_sum2[i] = 0.0; g_sq2[i] = 0.0; }
}

// ---------------- K1a: detect idx dtype (int32 vs int64) ----------------
// idx in [0, n), n < 2^31. Little-endian int64 => every odd 32-bit word is 0.
__global__ void k_detect(const int* w, int nk) {
    __shared__ int ok;
    if (threadIdx.x == 0) ok = 1;
    __syncthreads();
    int m = 64;
    if (nk < 128) m = nk / 2;
    if ((int)threadIdx.x < m) {
        if (w[2 * threadIdx.x + 1] != 0) ok = 0;  // benign race: only writes 0
    }
    __syncthreads();
    if (threadIdx.x == 0) g_is64 = ok;
}

// ---------------- K1b: histogram of idx (vectorized int4 loads) ----------------
__global__ void k_hist(const void* idxp, int nk) {
    int is64 = g_is64;
    int i  = blockIdx.x * blockDim.x + threadIdx.x;
    int st = gridDim.x * blockDim.x;
    if ((nk & 3) == 0) {
        const int4* p = (const int4*)idxp;
        if (is64) {
            int nq = nk >> 1;      // int64: int4 = 2 entries {x=lo0, z=lo1}
            for (int e = i; e < nq; e += st) {
                int4 v = p[e];
                atomicAdd(&g_count[v.x], 1);
                atomicAdd(&g_count[v.z], 1);
            }
        } else {
            int nq = nk >> 2;
            for (int e = i; e < nq; e += st) {
                int4 v = p[e];
                atomicAdd(&g_count[v.x], 1);
                atomicAdd(&g_count[v.y], 1);
                atomicAdd(&g_count[v.z], 1);
                atomicAdd(&g_count[v.w], 1);
            }
        }
    } else {
        if (is64) {
            const long long* p = (const long long*)idxp;
            for (int e = i; e < nk; e += st) atomicAdd(&g_count[(int)p[e]], 1);
        } else {
            const int* p = (const int*)idxp;
            for (int e = i; e < nk; e += st) atomicAdd(&g_count[p[e]], 1);
        }
    }
}

// ---------------- K2: T1 = feat @ W1 + b1 (128 rows/block, 4x8 tiles, f32x2)
// tx = tid&7 -> cols tx*8..+7 ; ty = tid>>3 -> rows ty*4..+3 ; + fused BN1 stats
static const int SMEM1 = (64 * 132 + 64 * 64 + 64) * 4;   // As + W1 + bias = 50.3KB
__global__ __launch_bounds__(256) void k_gemm1(const float* __restrict__ feat,
                                               const float* __restrict__ W1,
                                               const float* __restrict__ b1, int n) {
    extern __shared__ float sm[];
    float* As = sm;                 // As[k*132 + r], r < 128 (16B-aligned rows)
    float* Bs = sm + 64 * 132;      // W1 natural [k][c]
    float* bs = Bs + 64 * 64;

    int tid = threadIdx.x;
    int tx = tid & 7;         // cols tx*8 .. tx*8+7  (64)
    int ty = tid >> 3;        // rows ty*4 .. ty*4+3  (128)
    int row0 = blockIdx.x * 128;

    for (int t = tid; t < 64 * 16; t += 256)
        ((float4*)Bs)[t] = ((const float4*)W1)[t];
    if (tid < 64) bs[tid] = b1[tid];
    // feat tile: float4 loads, transpose into As
    for (int t = tid; t < 128 * 16; t += 256) {
        int r = t >> 4, q = t & 15;
        int gr = row0 + r;
        float4 v = (gr < n) ? ((const float4*)feat)[(size_t)gr * 16 + q]
                            : make_float4(0.f, 0.f, 0.f, 0.f);
        As[(4 * q + 0) * 132 + r] = v.x;
        As[(4 * q + 1) * 132 + r] = v.y;
        As[(4 * q + 2) * 132 + r] = v.z;
        As[(4 * q + 3) * 132 + r] = v.w;
    }
    __syncthreads();

    unsigned long long acc2[4][4];   // [row][colpair]; pair = cols 2j,2j+1 of the 8
#pragma unroll
    for (int i = 0; i < 4; i++)
#pragma unroll
        for (int j = 0; j < 4; j++) acc2[i][j] = 0ull;

#pragma unroll 4
    for (int k = 0; k < 64; k++) {
        float4 av = *(const float4*)&As[k * 132 + ty * 4];
        unsigned long long a2[4];
        DUP2(a2[0], av.x); DUP2(a2[1], av.y); DUP2(a2[2], av.z); DUP2(a2[3], av.w);
        F4U b0, b1v;
        b0.f  = *(const float4*)&Bs[k * 64 + tx * 8];
        b1v.f = *(const float4*)&Bs[k * 64 + tx * 8 + 4];
#pragma unroll
        for (int i = 0; i < 4; i++) {
            FFMA2(acc2[i][0], a2[i], b0.u[0]);
            FFMA2(acc2[i][1], a2[i], b0.u[1]);
            FFMA2(acc2[i][2], a2[i], b1v.u[0]);
            FFMA2(acc2[i][3], a2[i], b1v.u[1]);
        }
    }

    float4 bias0 = *(const float4*)&bs[tx * 8];
    float4 bias1 = *(const float4*)&bs[tx * 8 + 4];
    float sj[8], qj[8];
#pragma unroll
    for (int j = 0; j < 8; j++) { sj[j] = 0.f; qj[j] = 0.f; }

#pragma unroll
    for (int i = 0; i < 4; i++) {
        int gr = row0 + ty * 4 + i;
        if (gr < n) {
            float c[8];
            UNPK2(c[0], c[1], acc2[i][0]);
            UNPK2(c[2], c[3], acc2[i][1]);
            UNPK2(c[4], c[5], acc2[i][2]);
            UNPK2(c[6], c[7], acc2[i][3]);
            c[0] += bias0.x; c[1] += bias0.y; c[2] += bias0.z; c[3] += bias0.w;
            c[4] += bias1.x; c[5] += bias1.y; c[6] += bias1.z; c[7] += bias1.w;
            *(float4*)&g_T1[(size_t)gr * CMID + tx * 8]     = make_float4(c[0], c[1], c[2], c[3]);
            *(float4*)&g_T1[(size_t)gr * CMID + tx * 8 + 4] = make_float4(c[4], c[5], c[6], c[7]);
            float w = (float)g_count[gr];
#pragma unroll
            for (int j = 0; j < 8; j++) { sj[j] += w * c[j]; qj[j] += w * c[j] * c[j]; }
        }
    }

    // block-level stats reduction (reuse As: 2 x 32 x 64 floats = 16KB)
    __syncthreads();
    float* shs = As;
    float* shq = As + 2048;
#pragma unroll
    for (int j = 0; j < 8; j++) {
        shs[ty * 64 + tx * 8 + j] = sj[j];
        shq[ty * 64 + tx * 8 + j] = qj[j];
    }
    __syncthreads();
    if (tid < 64) {
        double s = 0.0, q = 0.0;
#pragma unroll
        for (int u = 0; u < 32; u++) { s += (double)shs[u * 64 + tid]; q += (double)shq[u * 64 + tid]; }
        int slot = blockIdx.x & (NSLOT - 1);
        atomicAdd(&g_sum1[slot * CMID + tid], s);
        atomicAdd(&g_sq1[slot * CMID + tid], q);
    }
}

// ---------------- finalize BN affine: s = g*rsqrt(var+eps), t = be - mean*s ------
template <int C>
__global__ void k_fin(const float* __restrict__ g, const float* __restrict__ be, double M) {
    int c = threadIdx.x;
    if (c >= C) return;
    const double* S = (C == CMID) ? g_sum1 : g_sum2;
    const double* Q = (C == CMID) ? g_sq1  : g_sq2;
    float* so = (C == CMID) ? g_s1 : g_s2;
    float* to = (C == CMID) ? g_t1 : g_t2;
    double s = 0.0, q = 0.0;
#pragma unroll
    for (int u = 0; u < NSLOT; u++) { s += S[u * C + c]; q += Q[u * C + c]; }
    double mean = s / M;
    double var  = q / M - mean * mean;
    double rs   = 1.0 / sqrt(var + BN_EPS);
    float  sc   = (float)((double)g[c] * rs);
    so[c] = sc;
    to[c] = (float)((double)be[c] - mean * (double)sc);
}

// ---------------- K4: T2 = relu(bn1(T1)) @ W2 + b2 (128 rows/block, 8x8, f32x2)
// tx = tid&15 -> cols tx*8..+7 ; ty = tid>>4 -> rows ty*8..+7
// + BN2 stats from f32 regs + fp16 (pre-BN2) store.
static const int SMEM2 = (64 * 132 + 64 * 128 + 128) * 4;  // As + W2 + bias = 66.8KB
__global__ __launch_bounds__(256) void k_gemm2(const float* __restrict__ W2,
                                               const float* __restrict__ b2, int n) {
    extern __shared__ float sm[];
    float* As  = sm;                 // As[k*132 + r], r < 128  (h1 transposed)
    float* Bs  = sm + 64 * 132;      // W2 natural [k][c] (full, 32KB)
    float* b2s = Bs + 64 * 128;

    int tid = threadIdx.x;
    int tx = tid & 15;        // cols tx*8 .. tx*8+7   (128)
    int ty = tid >> 4;        // rows ty*8 .. ty*8+7   (128)
    int row0 = blockIdx.x * 128;

    for (int t = tid; t < 64 * 32; t += 256)
        ((float4*)Bs)[t] = ((const float4*)W2)[t];
    if (tid < 128) b2s[tid] = b2[tid];
    // fill As with relu(bn1(T1)) — transposed [k][r]
    for (int t = tid; t < 128 * 64; t += 256) {
        int r = t >> 6, kk = t & 63;
        int gr = row0 + r;
        float v = (gr < n) ? g_T1[(size_t)gr * CMID + kk] : 0.0f;
        As[kk * 132 + r] = fmaxf(fmaf(g_s1[kk], v, g_t1[kk]), 0.0f);
    }
    __syncthreads();

    unsigned long long acc2[8][4];
#pragma unroll
    for (int i = 0; i < 8; i++)
#pragma unroll
        for (int j = 0; j < 4; j++) acc2[i][j] = 0ull;

#pragma unroll 2
    for (int k = 0; k < 64; k++) {
        float4 av0 = *(const float4*)&As[k * 132 + ty * 8];
        float4 av1 = *(const float4*)&As[k * 132 + ty * 8 + 4];
        unsigned long long a2[8];
        DUP2(a2[0], av0.x); DUP2(a2[1], av0.y); DUP2(a2[2], av0.z); DUP2(a2[3], av0.w);
        DUP2(a2[4], av1.x); DUP2(a2[5], av1.y); DUP2(a2[6], av1.z); DUP2(a2[7], av1.w);
        F4U b0, b1v;
        b0.f  = *(const float4*)&Bs[k * 128 + tx * 8];
        b1v.f = *(const float4*)&Bs[k * 128 + tx * 8 + 4];
#pragma unroll
        for (int i = 0; i < 8; i++) {
            FFMA2(acc2[i][0], a2[i], b0.u[0]);
            FFMA2(acc2[i][1], a2[i], b0.u[1]);
            FFMA2(acc2[i][2], a2[i], b1v.u[0]);
            FFMA2(acc2[i][3], a2[i], b1v.u[1]);
        }
    }

    float4 bias0 = *(const float4*)&b2s[tx * 8];
    float4 bias1 = *(const float4*)&b2s[tx * 8 + 4];
    float sj[8], qj[8];
#pragma unroll
    for (int j = 0; j < 8; j++) { sj[j] = 0.f; qj[j] = 0.f; }

#pragma unroll
    for (int i = 0; i < 8; i++) {
        int gr = row0 + ty * 8 + i;
        if (gr < n) {
            float c[8];
            UNPK2(c[0], c[1], acc2[i][0]);
            UNPK2(c[2], c[3], acc2[i][1]);
            UNPK2(c[4], c[5], acc2[i][2]);
            UNPK2(c[6], c[7], acc2[i][3]);
            c[0] += bias0.x; c[1] += bias0.y; c[2] += bias0.z; c[3] += bias0.w;
            c[4] += bias1.x; c[5] += bias1.y; c[6] += bias1.z; c[7] += bias1.w;
            float w = (float)g_count[gr];
#pragma unroll
            for (int j = 0; j < 8; j++) { sj[j] += w * c[j]; qj[j] += w * c[j] * c[j]; }
            union { uint4 u; __half2 h[4]; } pk;
            pk.h[0] = __floats2half2_rn(c[0], c[1]);
            pk.h[1] = __floats2half2_rn(c[2], c[3]);
            pk.h[2] = __floats2half2_rn(c[4], c[5]);
            pk.h[3] = __floats2half2_rn(c[6], c[7]);
            *(uint4*)&g_T2h[(size_t)gr * COUT + tx * 8] = pk.u;
        }
    }

    // block-level stats reduction (reuse As: 2 x 16 x 128 floats = 16KB)
    __syncthreads();
    float* shs = As;
    float* shq = As + 2048;
#pragma unroll
    for (int j = 0; j < 8; j++) {
        shs[ty * 128 + tx * 8 + j] = sj[j];
        shq[ty * 128 + tx * 8 + j] = qj[j];
    }
    __syncthreads();
    if (tid < 128) {
        double s = 0.0, q = 0.0;
#pragma unroll
        for (int u = 0; u < 16; u++) { s += (double)shs[u * 128 + tid]; q += (double)shq[u * 128 + tid]; }
        int slot = blockIdx.x & (NSLOT - 1);
        atomicAdd(&g_sum2[slot * COUT + tid], s);
        atomicAdd(&g_sq2[slot * COUT + tid], q);
    }
}

// ---------------- K6: gather + bn2 affine + relu + max over k (fp16 table) -------
// One warp per output point. Lane l owns channels 4l..4l+3.
__global__ __launch_bounds__(256) void k_gather(const void* __restrict__ idxp,
                                                float* __restrict__ out, int n, int k) {
    int warp = (blockIdx.x * blockDim.x + threadIdx.x) >> 5;
    int lane = threadIdx.x & 31;
    if (warp >= n) return;
    int is64 = g_is64;

    float4 s2 = *(const float4*)&g_s2[lane * 4];
    float4 t2 = *(const float4*)&g_t2[lane * 4];
    float m0 = 0.f, m1 = 0.f, m2 = 0.f, m3 = 0.f;   // relu => result >= 0

    if (k == 16) {
        int r_mine = 0;
        if (lane < 16) {
            if (is64) r_mine = (int)((const long long*)idxp)[(size_t)warp * 16 + lane];
            else      r_mine = ((const int*)idxp)[(size_t)warp * 16 + lane];
        }
#pragma unroll
        for (int j = 0; j < 16; j++) {
            int r = __shfl_sync(0xffffffffu, r_mine, j);
            uint2 v = *(const uint2*)&g_T2h[(size_t)r * COUT + lane * 4];
            float2 f01 = __half22float2(*(__half2*)&v.x);
            float2 f23 = __half22float2(*(__half2*)&v.y);
            m0 = fmaxf(m0, fmaf(s2.x, f01.x, t2.x));
            m1 = fmaxf(m1, fmaf(s2.y, f01.y, t2.y));
            m2 = fmaxf(m2, fmaf(s2.z, f23.x, t2.z));
            m3 = fmaxf(m3, fmaf(s2.w, f23.y, t2.w));
        }
    } else {
        for (int j = 0; j < k; j++) {
            int r;
            if (is64) r = (int)((const long long*)idxp)[(size_t)warp * k + j];
            else      r = ((const int*)idxp)[(size_t)warp * k + j];
            uint2 v = *(const uint2*)&g_T2h[(size_t)r * COUT + lane * 4];
            float2 f01 = __half22float2(*(__half2*)&v.x);
            float2 f23 = __half22float2(*(__half2*)&v.y);
            m0 = fmaxf(m0, fmaf(s2.x, f01.x, t2.x));
            m1 = fmaxf(m1, fmaf(s2.y, f01.y, t2.y));
            m2 = fmaxf(m2, fmaf(s2.z, f23.x, t2.z));
            m3 = fmaxf(m3, fmaf(s2.w, f23.y, t2.w));
        }
    }
    *(float4*)&out[(size_t)warp * COUT + lane * 4] = make_float4(m0, m1, m2, m3);
}

// ---------------- host launcher ----------------
extern "C" void kernel_launch(void* const* d_in, const int* in_sizes, int n_in,
                              void* d_out, int out_size) {
    const float* feat = (const float*)d_in[0];
    const void*  idx  = d_in[1];
    const float* W1   = (const float*)d_in[2];
    const float* b1   = (const float*)d_in[3];
    const float* g1   = (const float*)d_in[4];
    const float* be1  = (const float*)d_in[5];
    const float* W2   = (const float*)d_in[6];
    const float* b2   = (const float*)d_in[7];
    const float* g2   = (const float*)d_in[8];
    const float* be2  = (const float*)d_in[9];
    float* out = (float*)d_out;

    int n  = in_sizes[0] / CIN;      // 100000
    int nk = in_sizes[1];            // n * k
    int k  = nk / n;                 // 16
    double M = (double)nk;

    cudaFuncSetAttribute(k_gemm1, cudaFuncAttributeMaxDynamicSharedMemorySize, SMEM1);
    cudaFuncSetAttribute(k_gemm2, cudaFuncAttributeMaxDynamicSharedMemorySize, SMEM2);

    k_zero<<<(n + 255) / 256, 256>>>(n);
    k_detect<<<1, 64>>>((const int*)idx, nk);
    k_hist<<<512, 256>>>(idx, nk);

    k_gemm1<<<(n + 127) / 128, 256, SMEM1>>>(feat, W1, b1, n);
    k_fin<CMID><<<1, CMID>>>(g1, be1, M);

    k_gemm2<<<(n + 127) / 128, 256, SMEM2>>>(W2, b2, n);
    k_fin<COUT><<<1, COUT>>>(g2, be2, M);

    k_gather<<<(n + 7) / 8, 256>>>(idx, out, n, k);
}

// round 6
// speedup vs baseline: 1.0147x; 1.0147x over previous
#include <cuda_runtime.h>
#include <cuda_fp16.h>
#include <cstdint>

#define N_MAX 100000
#define CIN   64
#define CMID  64
#define COUT  128
#define BN_EPS 1e-5
#define NSLOT 16

// ---------------- device scratch (static: no allocations allowed) ----------------
__device__ int    g_count[N_MAX];
__device__ __half g_T1h[(size_t)N_MAX * CMID];   // feat @ W1 + b1, fp16 (12.8 MB)
__device__ __half g_T2h[(size_t)N_MAX * COUT];   // T2 pre-BN2, fp16 (25.6 MB)
__device__ double g_sum1[NSLOT * CMID], g_sq1[NSLOT * CMID];
__device__ double g_sum2[NSLOT * COUT], g_sq2[NSLOT * COUT];
__device__ float  g_s1[CMID], g_t1[CMID];
__device__ float  g_s2[COUT], g_t2[COUT];
__device__ int    g_is64;

// ---------------- K0: zero counters + accumulators ----------------
__global__ void k_zero(int n) {
    int i  = blockIdx.x * blockDim.x + threadIdx.x;
    int st = gridDim.x * blockDim.x;
    for (int j = i; j < n; j += st) g_count[j] = 0;
    if (i < NSLOT * CMID) { g_sum1[i] = 0.0; g_sq1[i] = 0.0; }
    if (i < NSLOT * COUT) { g_sum2[i] = 0.0; g_sq2[i] = 0.0; }
}

// ---------------- K1a: detect idx dtype (int32 vs int64) ----------------
// idx in [0, n), n < 2^31. Little-endian int64 => every odd 32-bit word is 0.
__global__ void k_detect(const int* w, int nk) {
    __shared__ int ok;
    if (threadIdx.x == 0) ok = 1;
    __syncthreads();
    int m = 64;
    if (nk < 128) m = nk / 2;
    if ((int)threadIdx.x < m) {
        if (w[2 * threadIdx.x + 1] != 0) ok = 0;  // benign race: only writes 0
    }
    __syncthreads();
    if (threadIdx.x == 0) g_is64 = ok;
}

// ---------------- K1b: histogram of idx (vectorized int4 loads) ----------------
__global__ void k_hist(const void* idxp, int nk) {
    int is64 = g_is64;
    int i  = blockIdx.x * blockDim.x + threadIdx.x;
    int st = gridDim.x * blockDim.x;
    if ((nk & 3) == 0) {
        const int4* p = (const int4*)idxp;
        if (is64) {
            int nq = nk >> 1;      // int64: int4 = 2 entries {x=lo0, z=lo1}
            for (int e = i; e < nq; e += st) {
                int4 v = p[e];
                atomicAdd(&g_count[v.x], 1);
                atomicAdd(&g_count[v.z], 1);
            }
        } else {
            int nq = nk >> 2;
            for (int e = i; e < nq; e += st) {
                int4 v = p[e];
                atomicAdd(&g_count[v.x], 1);
                atomicAdd(&g_count[v.y], 1);
                atomicAdd(&g_count[v.z], 1);
                atomicAdd(&g_count[v.w], 1);
            }
        }
    } else {
        if (is64) {
            const long long* p = (const long long*)idxp;
            for (int e = i; e < nk; e += st) atomicAdd(&g_count[(int)p[e]], 1);
        } else {
            const int* p = (const int*)idxp;
            for (int e = i; e < nk; e += st) atomicAdd(&g_count[p[e]], 1);
        }
    }
}

// ---------------- K2: T1 = feat @ W1 + b1 (128 rows/block, 8x4 tiles, scalar FFMA)
// tx = tid&15 -> cols tx*4..+3 ; ty = tid>>4 -> rows ty*8..+7 ; + fused BN1 stats
// As stride 132 -> 16B-aligned rows: a-loads are 2x LDS.128, b-load 1x LDS.128.
static const int SMEM1 = (64 * 132 + 64 * 64 + 64) * 4;   // As + W1 + bias = 50.3KB
__global__ __launch_bounds__(256) void k_gemm1(const float* __restrict__ feat,
                                               const float* __restrict__ W1,
                                               const float* __restrict__ b1, int n) {
    extern __shared__ float sm[];
    float* As = sm;                 // As[k*132 + r], r < 128
    float* Bs = sm + 64 * 132;      // W1 natural [k][c]
    float* bs = Bs + 64 * 64;

    int tid = threadIdx.x;
    int tx = tid & 15;        // cols tx*4 .. tx*4+3  (64)
    int ty = tid >> 4;        // rows ty*8 .. ty*8+7  (128)
    int row0 = blockIdx.x * 128;

    for (int t = tid; t < 64 * 16; t += 256)
        ((float4*)Bs)[t] = ((const float4*)W1)[t];
    if (tid < 64) bs[tid] = b1[tid];
    // feat tile: float4 loads, transpose into As
    for (int t = tid; t < 128 * 16; t += 256) {
        int r = t >> 4, q = t & 15;
        int gr = row0 + r;
        float4 v = (gr < n) ? ((const float4*)feat)[(size_t)gr * 16 + q]
                            : make_float4(0.f, 0.f, 0.f, 0.f);
        As[(4 * q + 0) * 132 + r] = v.x;
        As[(4 * q + 1) * 132 + r] = v.y;
        As[(4 * q + 2) * 132 + r] = v.z;
        As[(4 * q + 3) * 132 + r] = v.w;
    }
    __syncthreads();

    float acc[8][4];
#pragma unroll
    for (int i = 0; i < 8; i++)
#pragma unroll
        for (int j = 0; j < 4; j++) acc[i][j] = 0.0f;

#pragma unroll 4
    for (int k = 0; k < 64; k++) {
        float4 av0 = *(const float4*)&As[k * 132 + ty * 8];
        float4 av1 = *(const float4*)&As[k * 132 + ty * 8 + 4];
        float a[8] = {av0.x, av0.y, av0.z, av0.w, av1.x, av1.y, av1.z, av1.w};
        float4 bv = *(const float4*)&Bs[k * 64 + tx * 4];
#pragma unroll
        for (int i = 0; i < 8; i++) {
            acc[i][0] = fmaf(a[i], bv.x, acc[i][0]);
            acc[i][1] = fmaf(a[i], bv.y, acc[i][1]);
            acc[i][2] = fmaf(a[i], bv.z, acc[i][2]);
            acc[i][3] = fmaf(a[i], bv.w, acc[i][3]);
        }
    }

    float4 bias = *(const float4*)&bs[tx * 4];
    float sj[4] = {0, 0, 0, 0}, qj[4] = {0, 0, 0, 0};
#pragma unroll
    for (int i = 0; i < 8; i++) {
        int gr = row0 + ty * 8 + i;
        if (gr < n) {
            float4 o;
            o.x = acc[i][0] + bias.x; o.y = acc[i][1] + bias.y;
            o.z = acc[i][2] + bias.z; o.w = acc[i][3] + bias.w;
            union { uint2 u; __half2 h[2]; } pk;
            pk.h[0] = __floats2half2_rn(o.x, o.y);
            pk.h[1] = __floats2half2_rn(o.z, o.w);
            *(uint2*)&g_T1h[(size_t)gr * CMID + tx * 4] = pk.u;
            float w = (float)g_count[gr];
            sj[0] += w * o.x; qj[0] += w * o.x * o.x;
            sj[1] += w * o.y; qj[1] += w * o.y * o.y;
            sj[2] += w * o.z; qj[2] += w * o.z * o.z;
            sj[3] += w * o.w; qj[3] += w * o.w * o.w;
        }
    }

    // block-level stats reduction (reuse As: 2 x 16 x 64 floats)
    __syncthreads();
    float* shs = As;
    float* shq = As + 1024;
#pragma unroll
    for (int j = 0; j < 4; j++) {
        shs[ty * 64 + tx * 4 + j] = sj[j];
        shq[ty * 64 + tx * 4 + j] = qj[j];
    }
    __syncthreads();
    if (tid < 64) {
        double s = 0.0, q = 0.0;
#pragma unroll
        for (int u = 0; u < 16; u++) { s += (double)shs[u * 64 + tid]; q += (double)shq[u * 64 + tid]; }
        int slot = blockIdx.x & (NSLOT - 1);
        atomicAdd(&g_sum1[slot * CMID + tid], s);
        atomicAdd(&g_sq1[slot * CMID + tid], q);
    }
}

// ---------------- finalize BN affine: s = g*rsqrt(var+eps), t = be - mean*s ------
template <int C>
__global__ void k_fin(const float* __restrict__ g, const float* __restrict__ be, double M) {
    int c = threadIdx.x;
    if (c >= C) return;
    const double* S = (C == CMID) ? g_sum1 : g_sum2;
    const double* Q = (C == CMID) ? g_sq1  : g_sq2;
    float* so = (C == CMID) ? g_s1 : g_s2;
    float* to = (C == CMID) ? g_t1 : g_t2;
    double s = 0.0, q = 0.0;
#pragma unroll
    for (int u = 0; u < NSLOT; u++) { s += S[u * C + c]; q += Q[u * C + c]; }
    double mean = s / M;
    double var  = q / M - mean * mean;
    double rs   = 1.0 / sqrt(var + BN_EPS);
    float  sc   = (float)((double)g[c] * rs);
    so[c] = sc;
    to[c] = (float)((double)be[c] - mean * (double)sc);
}

// ---------------- K4: T2 = relu(bn1(T1)) @ W2 + b2 (128 rows/block, 8x8, scalar)
// tx = tid&15 -> cols tx*8..+7 ; ty = tid>>4 -> rows ty*8..+7
// Full W2 resident (32KB). Per k: 2 LDS.128 (a) + 2 LDS.128 (b) + 64 FFMA.
// + BN2 stats from f32 regs + fp16 (pre-BN2) store.
static const int SMEM2 = (64 * 132 + 64 * 128 + 128) * 4;  // As + W2 + bias = 66.8KB
__global__ __launch_bounds__(256) void k_gemm2(const float* __restrict__ W2,
                                               const float* __restrict__ b2, int n) {
    extern __shared__ float sm[];
    float* As  = sm;                 // As[k*132 + r], r < 128  (h1 transposed)
    float* Bs  = sm + 64 * 132;      // W2 natural [k][c] (full, 32KB)
    float* b2s = Bs + 64 * 128;

    int tid = threadIdx.x;
    int tx = tid & 15;        // cols tx*8 .. tx*8+7   (128)
    int ty = tid >> 4;        // rows ty*8 .. ty*8+7   (128)
    int row0 = blockIdx.x * 128;

    for (int t = tid; t < 64 * 32; t += 256)
        ((float4*)Bs)[t] = ((const float4*)W2)[t];
    if (tid < 128) b2s[tid] = b2[tid];
    // fill As with relu(bn1(T1))  (transposed [k][r]); T1 is fp16, load half2
    for (int t = tid; t < 128 * 32; t += 256) {
        int r = t >> 5, q = t & 31;          // q = half2 chunk (2 k's)
        int gr = row0 + r;
        float2 v = make_float2(0.f, 0.f);
        if (gr < n) {
            __half2 hv = *(const __half2*)&g_T1h[(size_t)gr * CMID + q * 2];
            v = __half22float2(hv);
        }
        int k0 = q * 2;
        As[(k0 + 0) * 132 + r] = fmaxf(fmaf(g_s1[k0 + 0], v.x, g_t1[k0 + 0]), 0.0f);
        As[(k0 + 1) * 132 + r] = fmaxf(fmaf(g_s1[k0 + 1], v.y, g_t1[k0 + 1]), 0.0f);
    }
    __syncthreads();

    float acc[8][8];
#pragma unroll
    for (int i = 0; i < 8; i++)
#pragma unroll
        for (int j = 0; j < 8; j++) acc[i][j] = 0.0f;

#pragma unroll 2
    for (int k = 0; k < 64; k++) {
        float4 av0 = *(const float4*)&As[k * 132 + ty * 8];
        float4 av1 = *(const float4*)&As[k * 132 + ty * 8 + 4];
        float a[8] = {av0.x, av0.y, av0.z, av0.w, av1.x, av1.y, av1.z, av1.w};
        float4 bv0 = *(const float4*)&Bs[k * 128 + tx * 8];
        float4 bv1 = *(const float4*)&Bs[k * 128 + tx * 8 + 4];
        float b[8] = {bv0.x, bv0.y, bv0.z, bv0.w, bv1.x, bv1.y, bv1.z, bv1.w};
#pragma unroll
        for (int i = 0; i < 8; i++)
#pragma unroll
            for (int j = 0; j < 8; j++)
                acc[i][j] = fmaf(a[i], b[j], acc[i][j]);
    }

    float4 bias0 = *(const float4*)&b2s[tx * 8];
    float4 bias1 = *(const float4*)&b2s[tx * 8 + 4];
    float bb[8] = {bias0.x, bias0.y, bias0.z, bias0.w, bias1.x, bias1.y, bias1.z, bias1.w};
    float sj[8], qj[8];
#pragma unroll
    for (int j = 0; j < 8; j++) { sj[j] = 0.f; qj[j] = 0.f; }

#pragma unroll
    for (int i = 0; i < 8; i++) {
        int gr = row0 + ty * 8 + i;
        if (gr < n) {
            float c[8];
#pragma unroll
            for (int j = 0; j < 8; j++) c[j] = acc[i][j] + bb[j];
            float w = (float)g_count[gr];
#pragma unroll
            for (int j = 0; j < 8; j++) { sj[j] += w * c[j]; qj[j] += w * c[j] * c[j]; }
            union { uint4 u; __half2 h[4]; } pk;
            pk.h[0] = __floats2half2_rn(c[0], c[1]);
            pk.h[1] = __floats2half2_rn(c[2], c[3]);
            pk.h[2] = __floats2half2_rn(c[4], c[5]);
            pk.h[3] = __floats2half2_rn(c[6], c[7]);
            *(uint4*)&g_T2h[(size_t)gr * COUT + tx * 8] = pk.u;
        }
    }

    // block-level stats reduction (reuse As: 2 x 16 x 128 floats = 16KB)
    __syncthreads();
    float* shs = As;
    float* shq = As + 2048;
#pragma unroll
    for (int j = 0; j < 8; j++) {
        shs[ty * 128 + tx * 8 + j] = sj[j];
        shq[ty * 128 + tx * 8 + j] = qj[j];
    }
    __syncthreads();
    if (tid < 128) {
        double s = 0.0, q = 0.0;
#pragma unroll
        for (int u = 0; u < 16; u++) { s += (double)shs[u * 128 + tid]; q += (double)shq[u * 128 + tid]; }
        int slot = blockIdx.x & (NSLOT - 1);
        atomicAdd(&g_sum2[slot * COUT + tid], s);
        atomicAdd(&g_sq2[slot * COUT + tid], q);
    }
}

// ---------------- K6: gather + bn2 affine + relu + max over k (fp16 table) -------
// One warp per output point. Lane l owns channels 4l..4l+3.
__global__ __launch_bounds__(256) void k_gather(const void* __restrict__ idxp,
                                                float* __restrict__ out, int n, int k) {
    int warp = (blockIdx.x * blockDim.x + threadIdx.x) >> 5;
    int lane = threadIdx.x & 31;
    if (warp >= n) return;
    int is64 = g_is64;

    float4 s2 = *(const float4*)&g_s2[lane * 4];
    float4 t2 = *(const float4*)&g_t2[lane * 4];
    float m0 = 0.f, m1 = 0.f, m2 = 0.f, m3 = 0.f;   // relu => result >= 0

    if (k == 16) {
        int r_mine = 0;
        if (lane < 16) {
            if (is64) r_mine = (int)((const long long*)idxp)[(size_t)warp * 16 + lane];
            else      r_mine = ((const int*)idxp)[(size_t)warp * 16 + lane];
        }
#pragma unroll
        for (int j = 0; j < 16; j++) {
            int r = __shfl_sync(0xffffffffu, r_mine, j);
            uint2 v = *(const uint2*)&g_T2h[(size_t)r * COUT + lane * 4];
            float2 f01 = __half22float2(*(__half2*)&v.x);
            float2 f23 = __half22float2(*(__half2*)&v.y);
            m0 = fmaxf(m0, fmaf(s2.x, f01.x, t2.x));
            m1 = fmaxf(m1, fmaf(s2.y, f01.y, t2.y));
            m2 = fmaxf(m2, fmaf(s2.z, f23.x, t2.z));
            m3 = fmaxf(m3, fmaf(s2.w, f23.y, t2.w));
        }
    } else {
        for (int j = 0; j < k; j++) {
            int r;
            if (is64) r = (int)((const long long*)idxp)[(size_t)warp * k + j];
            else      r = ((const int*)idxp)[(size_t)warp * k + j];
            uint2 v = *(const uint2*)&g_T2h[(size_t)r * COUT + lane * 4];
            float2 f01 = __half22float2(*(__half2*)&v.x);
            float2 f23 = __half22float2(*(__half2*)&v.y);
            m0 = fmaxf(m0, fmaf(s2.x, f01.x, t2.x));
            m1 = fmaxf(m1, fmaf(s2.y, f01.y, t2.y));
            m2 = fmaxf(m2, fmaf(s2.z, f23.x, t2.z));
            m3 = fmaxf(m3, fmaf(s2.w, f23.y, t2.w));
        }
    }
    *(float4*)&out[(size_t)warp * COUT + lane * 4] = make_float4(m0, m1, m2, m3);
}

// ---------------- host launcher ----------------
extern "C" void kernel_launch(void* const* d_in, const int* in_sizes, int n_in,
                              void* d_out, int out_size) {
    const float* feat = (const float*)d_in[0];
    const void*  idx  = d_in[1];
    const float* W1   = (const float*)d_in[2];
    const float* b1   = (const float*)d_in[3];
    const float* g1   = (const float*)d_in[4];
    const float* be1  = (const float*)d_in[5];
    const float* W2   = (const float*)d_in[6];
    const float* b2   = (const float*)d_in[7];
    const float* g2   = (const float*)d_in[8];
    const float* be2  = (const float*)d_in[9];
    float* out = (float*)d_out;

    int n  = in_sizes[0] / CIN;      // 100000
    int nk = in_sizes[1];            // n * k
    int k  = nk / n;                 // 16
    double M = (double)nk;

    cudaFuncSetAttribute(k_gemm1, cudaFuncAttributeMaxDynamicSharedMemorySize, SMEM1);
    cudaFuncSetAttribute(k_gemm2, cudaFuncAttributeMaxDynamicSharedMemorySize, SMEM2);

    k_zero<<<(n + 255) / 256, 256>>>(n);
    k_detect<<<1, 64>>>((const int*)idx, nk);
    k_hist<<<512, 256>>>(idx, nk);

    k_gemm1<<<(n + 127) / 128, 256, SMEM1>>>(feat, W1, b1, n);
    k_fin<CMID><<<1, CMID>>>(g1, be1, M);

    k_gemm2<<<(n + 127) / 128, 256, SMEM2>>>(W2, b2, n);
    k_fin<COUT><<<1, COUT>>>(g2, be2, M);

    k_gather<<<(n + 7) / 8, 256>>>(idx, out, n, k);
}

// round 7
// speedup vs baseline: 1.3383x; 1.3189x over previous
#include <cuda_runtime.h>
#include <cuda_fp16.h>
#include <cstdint>

#define N_MAX 100000
#define CIN   64
#define CMID  64
#define COUT  128
#define BN_EPS 1e-5
#define NSLOT 16

// ---------------- mma / ldmatrix helpers (sm_103a HMMA path) ----------------
__device__ __forceinline__ uint32_t smem_u32(const void* p) {
    return (uint32_t)__cvta_generic_to_shared(p);
}
#define LDMX4(r0, r1, r2, r3, addr) \
    asm volatile("ldmatrix.sync.aligned.m8n8.x4.shared.b16 {%0,%1,%2,%3}, [%4];" \
                 : "=r"(r0), "=r"(r1), "=r"(r2), "=r"(r3) : "r"(addr))
#define LDMX4T(r0, r1, r2, r3, addr) \
    asm volatile("ldmatrix.sync.aligned.m8n8.x4.trans.shared.b16 {%0,%1,%2,%3}, [%4];" \
                 : "=r"(r0), "=r"(r1), "=r"(r2), "=r"(r3) : "r"(addr))
#define MMA16816(d, a0, a1, a2, a3, b0, b1) \
    asm volatile("mma.sync.aligned.m16n8k16.row.col.f32.f16.f16.f32 " \
                 "{%0,%1,%2,%3}, {%4,%5,%6,%7}, {%8,%9}, {%0,%1,%2,%3};" \
                 : "+f"(d[0]), "+f"(d[1]), "+f"(d[2]), "+f"(d[3]) \
                 : "r"(a0), "r"(a1), "r"(a2), "r"(a3), "r"(b0), "r"(b1))

// ---------------- device scratch (static: no allocations allowed) ----------------
__device__ int    g_count[N_MAX];
__device__ __half g_W1h[CIN * CMID];
__device__ __half g_W2h[CMID * COUT];
__device__ __half g_T1h[(size_t)N_MAX * CMID];   // feat @ W1 + b1, fp16 (12.8 MB)
__device__ __half g_T2h[(size_t)N_MAX * COUT];   // T2 pre-BN2, fp16 (25.6 MB)
__device__ double g_sum1[NSLOT * CMID], g_sq1[NSLOT * CMID];
__device__ double g_sum2[NSLOT * COUT], g_sq2[NSLOT * COUT];
__device__ float  g_s1[CMID], g_t1[CMID];
__device__ float  g_s2[COUT], g_t2[COUT];
__device__ int    g_is64;

// ---------------- K0: zero counters + accumulators ----------------
__global__ void k_zero(int n) {
    int i  = blockIdx.x * blockDim.x + threadIdx.x;
    int st = gridDim.x * blockDim.x;
    for (int j = i; j < n; j += st) g_count[j] = 0;
    if (i < NSLOT * CMID) { g_sum1[i] = 0.0; g_sq1[i] = 0.0; }
    if (i < NSLOT * COUT) { g_sum2[i] = 0.0; g_sq2[i] = 0.0; }
}

// ---------------- K1a: detect idx dtype (int32 vs int64) ----------------
// idx in [0, n), n < 2^31. Little-endian int64 => every odd 32-bit word is 0.
__global__ void k_detect(const int* w, int nk) {
    __shared__ int ok;
    if (threadIdx.x == 0) ok = 1;
    __syncthreads();
    int m = 64;
    if (nk < 128) m = nk / 2;
    if ((int)threadIdx.x < m) {
        if (w[2 * threadIdx.x + 1] != 0) ok = 0;  // benign race: only writes 0
    }
    __syncthreads();
    if (threadIdx.x == 0) g_is64 = ok;
}

// ---------------- K1b: histogram of idx (vectorized int4 loads) ----------------
__global__ void k_hist(const void* idxp, int nk) {
    int is64 = g_is64;
    int i  = blockIdx.x * blockDim.x + threadIdx.x;
    int st = gridDim.x * blockDim.x;
    if ((nk & 3) == 0) {
        const int4* p = (const int4*)idxp;
        if (is64) {
            int nq = nk >> 1;      // int64: int4 = 2 entries {x=lo0, z=lo1}
            for (int e = i; e < nq; e += st) {
                int4 v = p[e];
                atomicAdd(&g_count[v.x], 1);
                atomicAdd(&g_count[v.z], 1);
            }
        } else {
            int nq = nk >> 2;
            for (int e = i; e < nq; e += st) {
                int4 v = p[e];
                atomicAdd(&g_count[v.x], 1);
                atomicAdd(&g_count[v.y], 1);
                atomicAdd(&g_count[v.z], 1);
                atomicAdd(&g_count[v.w], 1);
            }
        }
    } else {
        if (is64) {
            const long long* p = (const long long*)idxp;
            for (int e = i; e < nk; e += st) atomicAdd(&g_count[(int)p[e]], 1);
        } else {
            const int* p = (const int*)idxp;
            for (int e = i; e < nk; e += st) atomicAdd(&g_count[p[e]], 1);
        }
    }
}

// ---------------- K1c: convert weights to fp16 ----------------
__global__ void k_prep(const float* __restrict__ W1, const float* __restrict__ W2) {
    int i = blockIdx.x * blockDim.x + threadIdx.x;
    if (i < CIN * CMID)  g_W1h[i] = __float2half_rn(W1[i]);
    if (i < CMID * COUT) g_W2h[i] = __float2half_rn(W2[i]);
}

// ---------------- K2: T1 = feat @ W1 + b1 via HMMA (128 rows/block) --------------
// 8 warps; warp w owns rows w*16..+15, all 64 cols. m16n8k16, 4 k-steps.
// As stride 72 halves (144B): rows hit distinct 16B phases mod 128B -> conflict-free.
__global__ __launch_bounds__(256) void k_gemm1(const float* __restrict__ feat,
                                               const float* __restrict__ b1, int n) {
    __shared__ __half As[128 * 72];
    __shared__ __half Bs[64 * 72];
    __shared__ float  bias[64];

    int tid = threadIdx.x;
    int row0 = blockIdx.x * 128;

    // Bs <- W1h  (rows of 64 halves = 8 uint4)
    for (int t = tid; t < 64 * 8; t += 256) {
        int r = t >> 3, q = t & 7;
        ((uint4*)&Bs[r * 72])[q] = ((const uint4*)&g_W1h[r * CMID])[q];
    }
    if (tid < 64) bias[tid] = b1[tid];
    // As <- feat (f32 -> f16)
    for (int t = tid; t < 128 * 16; t += 256) {
        int r = t >> 4, q = t & 15;
        int gr = row0 + r;
        float4 v = (gr < n) ? ((const float4*)feat)[(size_t)gr * 16 + q]
                            : make_float4(0.f, 0.f, 0.f, 0.f);
        __half2 h0 = __floats2half2_rn(v.x, v.y);
        __half2 h1 = __floats2half2_rn(v.z, v.w);
        uint2 pk;
        pk.x = *(uint32_t*)&h0; pk.y = *(uint32_t*)&h1;
        *(uint2*)&As[r * 72 + q * 4] = pk;
    }
    __syncthreads();

    int w = tid >> 5, lane = tid & 31;
    int lr = (lane & 7) + ((lane >> 3) & 1) * 8;   // tile-row within 16
    int lc = (lane >> 4) * 8;                      // tile-col select
    uint32_t abase = smem_u32(As), bbase = smem_u32(Bs);

    float acc[8][4];
#pragma unroll
    for (int i = 0; i < 8; i++)
#pragma unroll
        for (int j = 0; j < 4; j++) acc[i][j] = 0.0f;

#pragma unroll
    for (int ks = 0; ks < 4; ks++) {
        int k0 = ks * 16;
        uint32_t a0, a1, a2, a3;
        LDMX4(a0, a1, a2, a3, abase + (uint32_t)(((w * 16 + lr) * 72 + k0 + lc) * 2));
        uint32_t bb[8][2];
#pragma unroll
        for (int nt2 = 0; nt2 < 4; nt2++) {
            uint32_t r0, r1, r2, r3;
            LDMX4T(r0, r1, r2, r3, bbase + (uint32_t)(((k0 + lr) * 72 + nt2 * 16 + lc) * 2));
            bb[nt2 * 2][0] = r0;  bb[nt2 * 2][1] = r1;
            bb[nt2 * 2 + 1][0] = r2;  bb[nt2 * 2 + 1][1] = r3;
        }
#pragma unroll
        for (int nt = 0; nt < 8; nt++)
            MMA16816(acc[nt], a0, a1, a2, a3, bb[nt][0], bb[nt][1]);
    }

    // epilogue: d0,d1 -> (row, c/c+1); d2,d3 -> (row+8, c/c+1)
    int re = row0 + w * 16 + (lane >> 2);
    int cb = (lane & 3) * 2;
#pragma unroll
    for (int nt = 0; nt < 8; nt++) {
        int c = nt * 8 + cb;
        float bx = bias[c], by = bias[c + 1];
        if (re < n) {
            __half2 h = __floats2half2_rn(acc[nt][0] + bx, acc[nt][1] + by);
            *(__half2*)&g_T1h[(size_t)re * CMID + c] = h;
        }
        if (re + 8 < n) {
            __half2 h = __floats2half2_rn(acc[nt][2] + bx, acc[nt][3] + by);
            *(__half2*)&g_T1h[(size_t)(re + 8) * CMID + c] = h;
        }
    }
}

// ---------------- K3/K5: count-weighted channel stats over fp16 table -------------
template <int C>
__global__ __launch_bounds__(256) void k_statsw(int n) {
    const __half* T = (C == CMID) ? g_T1h : g_T2h;
    double* dS = (C == CMID) ? g_sum1 : g_sum2;
    double* dQ = (C == CMID) ? g_sq1  : g_sq2;
    const int C2 = C / 2;
    const int RL = 256 / C2;      // rows in flight per block (8 or 4)
    int tid = threadIdx.x;
    int ch = tid % C2;            // half2 column
    int ry = tid / C2;

    float s0 = 0.f, s1 = 0.f, q0 = 0.f, q1 = 0.f;
    for (int r = blockIdx.x * RL + ry; r < n; r += gridDim.x * RL) {
        float wv = (float)g_count[r];
        float2 v = __half22float2(*(const __half2*)&T[(size_t)r * C + ch * 2]);
        s0 += wv * v.x; q0 += wv * v.x * v.x;
        s1 += wv * v.y; q1 += wv * v.y * v.y;
    }
    __shared__ float sh[4][256];
    sh[0][tid] = s0; sh[1][tid] = s1; sh[2][tid] = q0; sh[3][tid] = q1;
    __syncthreads();
    if (ry == 0) {
#pragma unroll
        for (int u = 1; u < RL; u++) {
            s0 += sh[0][ch + u * C2]; s1 += sh[1][ch + u * C2];
            q0 += sh[2][ch + u * C2]; q1 += sh[3][ch + u * C2];
        }
        int slot = blockIdx.x & (NSLOT - 1);
        atomicAdd(&dS[slot * C + ch * 2],     (double)s0);
        atomicAdd(&dS[slot * C + ch * 2 + 1], (double)s1);
        atomicAdd(&dQ[slot * C + ch * 2],     (double)q0);
        atomicAdd(&dQ[slot * C + ch * 2 + 1], (double)q1);
    }
}

// ---------------- finalize BN affine: s = g*rsqrt(var+eps), t = be - mean*s ------
template <int C>
__global__ void k_fin(const float* __restrict__ g, const float* __restrict__ be, double M) {
    int c = threadIdx.x;
    if (c >= C) return;
    const double* S = (C == CMID) ? g_sum1 : g_sum2;
    const double* Q = (C == CMID) ? g_sq1  : g_sq2;
    float* so = (C == CMID) ? g_s1 : g_s2;
    float* to = (C == CMID) ? g_t1 : g_t2;
    double s = 0.0, q = 0.0;
#pragma unroll
    for (int u = 0; u < NSLOT; u++) { s += S[u * C + c]; q += Q[u * C + c]; }
    double mean = s / M;
    double var  = q / M - mean * mean;
    double rs   = 1.0 / sqrt(var + BN_EPS);
    float  sc   = (float)((double)g[c] * rs);
    so[c] = sc;
    to[c] = (float)((double)be[c] - mean * (double)sc);
}

// ---------------- K4: T2 = relu(bn1(T1)) @ W2 + b2 via HMMA (64 rows/block) ------
// 8 warps: wm = w&3 -> rows wm*16..+15 (64); wn = w>>2 -> cols wn*64..+63 (128).
__global__ __launch_bounds__(256) void k_gemm2(const float* __restrict__ b2, int n) {
    __shared__ __half As[64 * 72];
    __shared__ __half Bs[64 * 136];
    __shared__ float  bias[128];

    int tid = threadIdx.x;
    int row0 = blockIdx.x * 64;

    // Bs <- W2h (rows of 128 halves = 16 uint4); stride 136 halves (272B)
    for (int t = tid; t < 64 * 16; t += 256) {
        int r = t >> 4, q = t & 15;
        ((uint4*)&Bs[r * 136])[q] = ((const uint4*)&g_W2h[r * COUT])[q];
    }
    if (tid < 128) bias[tid] = b2[tid];
    // As <- relu(bn1(T1h)) in fp16 (rows of 64 halves = 8 uint4 chunks)
    for (int t = tid; t < 64 * 8; t += 256) {
        int r = t >> 3, q = t & 7;
        int gr = row0 + r;
        uint4 hv = make_uint4(0u, 0u, 0u, 0u);
        if (gr < n) hv = *(const uint4*)&g_T1h[(size_t)gr * CMID + q * 8];
        uint32_t* hw = &hv.x;
        uint4 ov;
        uint32_t* ow = &ov.x;
#pragma unroll
        for (int j = 0; j < 4; j++) {
            int kc = q * 8 + j * 2;
            float2 f = __half22float2(*(__half2*)&hw[j]);
            f.x = fmaxf(fmaf(g_s1[kc],     f.x, g_t1[kc]),     0.0f);
            f.y = fmaxf(fmaf(g_s1[kc + 1], f.y, g_t1[kc + 1]), 0.0f);
            __half2 h = __floats2half2_rn(f.x, f.y);
            ow[j] = *(uint32_t*)&h;
        }
        *(uint4*)&As[r * 72 + q * 8] = ov;
    }
    __syncthreads();

    int w = tid >> 5, lane = tid & 31;
    int wm = w & 3, wn = w >> 2;
    int lr = (lane & 7) + ((lane >> 3) & 1) * 8;
    int lc = (lane >> 4) * 8;
    uint32_t abase = smem_u32(As), bbase = smem_u32(Bs);

    float acc[8][4];
#pragma unroll
    for (int i = 0; i < 8; i++)
#pragma unroll
        for (int j = 0; j < 4; j++) acc[i][j] = 0.0f;

#pragma unroll
    for (int ks = 0; ks < 4; ks++) {
        int k0 = ks * 16;
        uint32_t a0, a1, a2, a3;
        LDMX4(a0, a1, a2, a3, abase + (uint32_t)(((wm * 16 + lr) * 72 + k0 + lc) * 2));
        uint32_t bb[8][2];
#pragma unroll
        for (int nt2 = 0; nt2 < 4; nt2++) {
            uint32_t r0, r1, r2, r3;
            LDMX4T(r0, r1, r2, r3,
                   bbase + (uint32_t)(((k0 + lr) * 136 + wn * 64 + nt2 * 16 + lc) * 2));
            bb[nt2 * 2][0] = r0;  bb[nt2 * 2][1] = r1;
            bb[nt2 * 2 + 1][0] = r2;  bb[nt2 * 2 + 1][1] = r3;
        }
#pragma unroll
        for (int nt = 0; nt < 8; nt++)
            MMA16816(acc[nt], a0, a1, a2, a3, bb[nt][0], bb[nt][1]);
    }

    int re = row0 + wm * 16 + (lane >> 2);
    int cb = wn * 64 + (lane & 3) * 2;
#pragma unroll
    for (int nt = 0; nt < 8; nt++) {
        int c = cb + nt * 8;
        float bx = bias[c], by = bias[c + 1];
        if (re < n) {
            __half2 h = __floats2half2_rn(acc[nt][0] + bx, acc[nt][1] + by);
            *(__half2*)&g_T2h[(size_t)re * COUT + c] = h;
        }
        if (re + 8 < n) {
            __half2 h = __floats2half2_rn(acc[nt][2] + bx, acc[nt][3] + by);
            *(__half2*)&g_T2h[(size_t)(re + 8) * COUT + c] = h;
        }
    }
}

// ---------------- K6: gather + bn2 affine + relu + max over k (fp16 table) -------
// One warp per output point. Lane l owns channels 4l..4l+3.
__global__ __launch_bounds__(256) void k_gather(const void* __restrict__ idxp,
                                                float* __restrict__ out, int n, int k) {
    int warp = (blockIdx.x * blockDim.x + threadIdx.x) >> 5;
    int lane = threadIdx.x & 31;
    if (warp >= n) return;
    int is64 = g_is64;

    float4 s2 = *(const float4*)&g_s2[lane * 4];
    float4 t2 = *(const float4*)&g_t2[lane * 4];
    float m0 = 0.f, m1 = 0.f, m2 = 0.f, m3 = 0.f;   // relu => result >= 0

    if (k == 16) {
        int r_mine = 0;
        if (lane < 16) {
            if (is64) r_mine = (int)((const long long*)idxp)[(size_t)warp * 16 + lane];
            else      r_mine = ((const int*)idxp)[(size_t)warp * 16 + lane];
        }
#pragma unroll
        for (int j = 0; j < 16; j++) {
            int r = __shfl_sync(0xffffffffu, r_mine, j);
            uint2 v = *(const uint2*)&g_T2h[(size_t)r * COUT + lane * 4];
            float2 f01 = __half22float2(*(__half2*)&v.x);
            float2 f23 = __half22float2(*(__half2*)&v.y);
            m0 = fmaxf(m0, fmaf(s2.x, f01.x, t2.x));
            m1 = fmaxf(m1, fmaf(s2.y, f01.y, t2.y));
            m2 = fmaxf(m2, fmaf(s2.z, f23.x, t2.z));
            m3 = fmaxf(m3, fmaf(s2.w, f23.y, t2.w));
        }
    } else {
        for (int j = 0; j < k; j++) {
            int r;
            if (is64) r = (int)((const long long*)idxp)[(size_t)warp * k + j];
            else      r = ((const int*)idxp)[(size_t)warp * k + j];
            uint2 v = *(const uint2*)&g_T2h[(size_t)r * COUT + lane * 4];
            float2 f01 = __half22float2(*(__half2*)&v.x);
            float2 f23 = __half22float2(*(__half2*)&v.y);
            m0 = fmaxf(m0, fmaf(s2.x, f01.x, t2.x));
            m1 = fmaxf(m1, fmaf(s2.y, f01.y, t2.y));
            m2 = fmaxf(m2, fmaf(s2.z, f23.x, t2.z));
            m3 = fmaxf(m3, fmaf(s2.w, f23.y, t2.w));
        }
    }
    *(float4*)&out[(size_t)warp * COUT + lane * 4] = make_float4(m0, m1, m2, m3);
}

// ---------------- host launcher ----------------
extern "C" void kernel_launch(void* const* d_in, const int* in_sizes, int n_in,
                              void* d_out, int out_size) {
    const float* feat = (const float*)d_in[0];
    const void*  idx  = d_in[1];
    const float* W1   = (const float*)d_in[2];
    const float* b1   = (const float*)d_in[3];
    const float* g1   = (const float*)d_in[4];
    const float* be1  = (const float*)d_in[5];
    const float* W2   = (const float*)d_in[6];
    const float* b2   = (const float*)d_in[7];
    const float* g2   = (const float*)d_in[8];
    const float* be2  = (const float*)d_in[9];
    float* out = (float*)d_out;

    int n  = in_sizes[0] / CIN;      // 100000
    int nk = in_sizes[1];            // n * k
    int k  = nk / n;                 // 16
    double M = (double)nk;

    k_zero<<<(n + 255) / 256, 256>>>(n);
    k_detect<<<1, 64>>>((const int*)idx, nk);
    k_hist<<<512, 256>>>(idx, nk);
    k_prep<<<(CMID * COUT + 255) / 256, 256>>>(W1, W2);

    k_gemm1<<<(n + 127) / 128, 256>>>(feat, b1, n);
    k_statsw<CMID><<<592, 256>>>(n);
    k_fin<CMID><<<1, CMID>>>(g1, be1, M);

    k_gemm2<<<(n + 63) / 64, 256>>>(b2, n);
    k_statsw<COUT><<<592, 256>>>(n);
    k_fin<COUT><<<1, COUT>>>(g2, be2, M);

    k_gather<<<(n + 7) / 8, 256>>>(idx, out, n, k);
}

// round 8
// speedup vs baseline: 1.4225x; 1.0629x over previous
#include <cuda_runtime.h>
#include <cuda_fp16.h>
#include <cstdint>

#define N_MAX 100000
#define CIN   64
#define CMID  64
#define COUT  128
#define BN_EPS 1e-5
#define NSLOT 16

// ---------------- mma / ldmatrix helpers (sm_103a HMMA path) ----------------
__device__ __forceinline__ uint32_t smem_u32(const void* p) {
    return (uint32_t)__cvta_generic_to_shared(p);
}
#define LDMX4(r0, r1, r2, r3, addr) \
    asm volatile("ldmatrix.sync.aligned.m8n8.x4.shared.b16 {%0,%1,%2,%3}, [%4];" \
                 : "=r"(r0), "=r"(r1), "=r"(r2), "=r"(r3) : "r"(addr))
#define LDMX4T(r0, r1, r2, r3, addr) \
    asm volatile("ldmatrix.sync.aligned.m8n8.x4.trans.shared.b16 {%0,%1,%2,%3}, [%4];" \
                 : "=r"(r0), "=r"(r1), "=r"(r2), "=r"(r3) : "r"(addr))
#define MMA16816(d, a0, a1, a2, a3, b0, b1) \
    asm volatile("mma.sync.aligned.m16n8k16.row.col.f32.f16.f16.f32 " \
                 "{%0,%1,%2,%3}, {%4,%5,%6,%7}, {%8,%9}, {%0,%1,%2,%3};" \
                 : "+f"(d[0]), "+f"(d[1]), "+f"(d[2]), "+f"(d[3]) \
                 : "r"(a0), "r"(a1), "r"(a2), "r"(a3), "r"(b0), "r"(b1))

// ---------------- device scratch (static: no allocations allowed) ----------------
__device__ int    g_count[N_MAX];
__device__ __half g_T1h[(size_t)N_MAX * CMID];   // feat @ W1 + b1, fp16 (12.8 MB)
__device__ __half g_T2h[(size_t)N_MAX * COUT];   // T2 pre-BN2, fp16 (25.6 MB)
__device__ double g_sum1[NSLOT * CMID], g_sq1[NSLOT * CMID];
__device__ double g_sum2[NSLOT * COUT], g_sq2[NSLOT * COUT];
__device__ float  g_s1[CMID], g_t1[CMID];
__device__ float  g_s2[COUT], g_t2[COUT];
__device__ int    g_is64;

// ---------------- K0: zero counters + accumulators ----------------
__global__ void k_zero(int n) {
    int i  = blockIdx.x * blockDim.x + threadIdx.x;
    int st = gridDim.x * blockDim.x;
    for (int j = i; j < n; j += st) g_count[j] = 0;
    if (i < NSLOT * CMID) { g_sum1[i] = 0.0; g_sq1[i] = 0.0; }
    if (i < NSLOT * COUT) { g_sum2[i] = 0.0; g_sq2[i] = 0.0; }
}

// ---------------- K1a: detect idx dtype (int32 vs int64) ----------------
// idx in [0, n), n < 2^31. Little-endian int64 => every odd 32-bit word is 0.
__global__ void k_detect(const int* w, int nk) {
    __shared__ int ok;
    if (threadIdx.x == 0) ok = 1;
    __syncthreads();
    int m = 64;
    if (nk < 128) m = nk / 2;
    if ((int)threadIdx.x < m) {
        if (w[2 * threadIdx.x + 1] != 0) ok = 0;  // benign race: only writes 0
    }
    __syncthreads();
    if (threadIdx.x == 0) g_is64 = ok;
}

// ---------------- K1b: histogram of idx (vectorized int4 loads) ----------------
__global__ void k_hist(const void* idxp, int nk) {
    int is64 = g_is64;
    int i  = blockIdx.x * blockDim.x + threadIdx.x;
    int st = gridDim.x * blockDim.x;
    if ((nk & 3) == 0) {
        const int4* p = (const int4*)idxp;
        if (is64) {
            int nq = nk >> 1;      // int64: int4 = 2 entries {x=lo0, z=lo1}
            for (int e = i; e < nq; e += st) {
                int4 v = p[e];
                atomicAdd(&g_count[v.x], 1);
                atomicAdd(&g_count[v.z], 1);
            }
        } else {
            int nq = nk >> 2;
            for (int e = i; e < nq; e += st) {
                int4 v = p[e];
                atomicAdd(&g_count[v.x], 1);
                atomicAdd(&g_count[v.y], 1);
                atomicAdd(&g_count[v.z], 1);
                atomicAdd(&g_count[v.w], 1);
            }
        }
    } else {
        if (is64) {
            const long long* p = (const long long*)idxp;
            for (int e = i; e < nk; e += st) atomicAdd(&g_count[(int)p[e]], 1);
        } else {
            const int* p = (const int*)idxp;
            for (int e = i; e < nk; e += st) atomicAdd(&g_count[p[e]], 1);
        }
    }
}

// ---------------- K2: T1 = feat @ W1 + b1 via HMMA (128 rows/block) --------------
// 8 warps; warp w owns rows w*16..+15, all 64 cols. m16n8k16, 4 k-steps.
// Fused: W1 f32->f16 conversion in Bs fill; weighted BN1 stats in epilogue.
__global__ __launch_bounds__(256) void k_gemm1(const float* __restrict__ feat,
                                               const float* __restrict__ W1,
                                               const float* __restrict__ b1, int n) {
    __shared__ __half As[128 * 72];
    __shared__ __half Bs[64 * 72];
    __shared__ float  bias[64];
    __shared__ float  shs[8 * 64], shq[8 * 64];

    int tid = threadIdx.x;
    int row0 = blockIdx.x * 128;

    // Bs <- f16(W1)
    for (int t = tid; t < 64 * 16; t += 256) {
        int r = t >> 4, q = t & 15;
        float4 v = ((const float4*)W1)[r * 16 + q];
        __half2 h0 = __floats2half2_rn(v.x, v.y);
        __half2 h1 = __floats2half2_rn(v.z, v.w);
        uint2 pk; pk.x = *(uint32_t*)&h0; pk.y = *(uint32_t*)&h1;
        *(uint2*)&Bs[r * 72 + q * 4] = pk;
    }
    if (tid < 64) bias[tid] = b1[tid];
    // As <- f16(feat)
    for (int t = tid; t < 128 * 16; t += 256) {
        int r = t >> 4, q = t & 15;
        int gr = row0 + r;
        float4 v = (gr < n) ? ((const float4*)feat)[(size_t)gr * 16 + q]
                            : make_float4(0.f, 0.f, 0.f, 0.f);
        __half2 h0 = __floats2half2_rn(v.x, v.y);
        __half2 h1 = __floats2half2_rn(v.z, v.w);
        uint2 pk; pk.x = *(uint32_t*)&h0; pk.y = *(uint32_t*)&h1;
        *(uint2*)&As[r * 72 + q * 4] = pk;
    }
    __syncthreads();

    int w = tid >> 5, lane = tid & 31;
    int lr = (lane & 7) + ((lane >> 3) & 1) * 8;   // tile-row within 16
    int lc = (lane >> 4) * 8;                      // tile-col select
    uint32_t abase = smem_u32(As), bbase = smem_u32(Bs);

    float acc[8][4];
#pragma unroll
    for (int i = 0; i < 8; i++)
#pragma unroll
        for (int j = 0; j < 4; j++) acc[i][j] = 0.0f;

#pragma unroll
    for (int ks = 0; ks < 4; ks++) {
        int k0 = ks * 16;
        uint32_t a0, a1, a2, a3;
        LDMX4(a0, a1, a2, a3, abase + (uint32_t)(((w * 16 + lr) * 72 + k0 + lc) * 2));
        uint32_t bb[8][2];
#pragma unroll
        for (int nt2 = 0; nt2 < 4; nt2++) {
            uint32_t r0, r1, r2, r3;
            LDMX4T(r0, r1, r2, r3, bbase + (uint32_t)(((k0 + lr) * 72 + nt2 * 16 + lc) * 2));
            bb[nt2 * 2][0] = r0;  bb[nt2 * 2][1] = r1;
            bb[nt2 * 2 + 1][0] = r2;  bb[nt2 * 2 + 1][1] = r3;
        }
#pragma unroll
        for (int nt = 0; nt < 8; nt++)
            MMA16816(acc[nt], a0, a1, a2, a3, bb[nt][0], bb[nt][1]);
    }

    // epilogue: store fp16 T1 + weighted stats
    int re = row0 + w * 16 + (lane >> 2);
    int cb = (lane & 3) * 2;
    float w0 = (re < n)     ? (float)g_count[re]     : 0.f;
    float w1 = (re + 8 < n) ? (float)g_count[re + 8] : 0.f;
#pragma unroll
    for (int nt = 0; nt < 8; nt++) {
        int c = nt * 8 + cb;
        float bx = bias[c], by = bias[c + 1];
        float v0 = acc[nt][0] + bx, v1 = acc[nt][1] + by;
        float v2 = acc[nt][2] + bx, v3 = acc[nt][3] + by;
        if (re < n) {
            __half2 h = __floats2half2_rn(v0, v1);
            *(__half2*)&g_T1h[(size_t)re * CMID + c] = h;
        }
        if (re + 8 < n) {
            __half2 h = __floats2half2_rn(v2, v3);
            *(__half2*)&g_T1h[(size_t)(re + 8) * CMID + c] = h;
        }
        float s0 = w0 * v0 + w1 * v2, s1 = w0 * v1 + w1 * v3;
        float q0 = w0 * v0 * v0 + w1 * v2 * v2, q1 = w0 * v1 * v1 + w1 * v3 * v3;
#pragma unroll
        for (int m = 4; m < 32; m <<= 1) {
            s0 += __shfl_xor_sync(0xffffffffu, s0, m);
            s1 += __shfl_xor_sync(0xffffffffu, s1, m);
            q0 += __shfl_xor_sync(0xffffffffu, q0, m);
            q1 += __shfl_xor_sync(0xffffffffu, q1, m);
        }
        if (lane < 4) {
            shs[w * 64 + c] = s0;  shs[w * 64 + c + 1] = s1;
            shq[w * 64 + c] = q0;  shq[w * 64 + c + 1] = q1;
        }
    }
    __syncthreads();
    if (tid < 64) {
        double s = 0.0, q = 0.0;
#pragma unroll
        for (int u = 0; u < 8; u++) { s += (double)shs[u * 64 + tid]; q += (double)shq[u * 64 + tid]; }
        int slot = blockIdx.x & (NSLOT - 1);
        atomicAdd(&g_sum1[slot * CMID + tid], s);
        atomicAdd(&g_sq1[slot * CMID + tid], q);
    }
}

// ---------------- finalize BN affine: s = g*rsqrt(var+eps), t = be - mean*s ------
template <int C>
__global__ void k_fin(const float* __restrict__ g, const float* __restrict__ be, double M) {
    int c = threadIdx.x;
    if (c >= C) return;
    const double* S = (C == CMID) ? g_sum1 : g_sum2;
    const double* Q = (C == CMID) ? g_sq1  : g_sq2;
    float* so = (C == CMID) ? g_s1 : g_s2;
    float* to = (C == CMID) ? g_t1 : g_t2;
    double s = 0.0, q = 0.0;
#pragma unroll
    for (int u = 0; u < NSLOT; u++) { s += S[u * C + c]; q += Q[u * C + c]; }
    double mean = s / M;
    double var  = q / M - mean * mean;
    double rs   = 1.0 / sqrt(var + BN_EPS);
    float  sc   = (float)((double)g[c] * rs);
    so[c] = sc;
    to[c] = (float)((double)be[c] - mean * (double)sc);
}

// ---------------- K4: T2 = relu(bn1(T1)) @ W2 + b2 via HMMA (64 rows/block) ------
// 8 warps: wm = w&3 -> rows wm*16..+15 (64); wn = w>>2 -> cols wn*64..+63 (128).
// Fused: W2 f32->f16 in Bs fill; BN1 affine in As fill; BN2 stats in epilogue.
__global__ __launch_bounds__(256) void k_gemm2(const float* __restrict__ W2,
                                               const float* __restrict__ b2, int n) {
    __shared__ __half As[64 * 72];
    __shared__ __half Bs[64 * 136];
    __shared__ float  bias[128];
    __shared__ float  shs[8 * 64], shq[8 * 64];

    int tid = threadIdx.x;
    int row0 = blockIdx.x * 64;

    // Bs <- f16(W2); stride 136 halves (272B)
    for (int t = tid; t < 64 * 32; t += 256) {
        int r = t >> 5, q = t & 31;
        float4 v = ((const float4*)W2)[r * 32 + q];
        __half2 h0 = __floats2half2_rn(v.x, v.y);
        __half2 h1 = __floats2half2_rn(v.z, v.w);
        uint2 pk; pk.x = *(uint32_t*)&h0; pk.y = *(uint32_t*)&h1;
        *(uint2*)&Bs[r * 136 + q * 4] = pk;
    }
    if (tid < 128) bias[tid] = b2[tid];
    // As <- relu(bn1(T1h)) in fp16
    for (int t = tid; t < 64 * 8; t += 256) {
        int r = t >> 3, q = t & 7;
        int gr = row0 + r;
        uint4 hv = make_uint4(0u, 0u, 0u, 0u);
        if (gr < n) hv = *(const uint4*)&g_T1h[(size_t)gr * CMID + q * 8];
        uint32_t* hw = &hv.x;
        uint4 ov;
        uint32_t* ow = &ov.x;
#pragma unroll
        for (int j = 0; j < 4; j++) {
            int kc = q * 8 + j * 2;
            float2 f = __half22float2(*(__half2*)&hw[j]);
            f.x = fmaxf(fmaf(g_s1[kc],     f.x, g_t1[kc]),     0.0f);
            f.y = fmaxf(fmaf(g_s1[kc + 1], f.y, g_t1[kc + 1]), 0.0f);
            __half2 h = __floats2half2_rn(f.x, f.y);
            ow[j] = *(uint32_t*)&h;
        }
        *(uint4*)&As[r * 72 + q * 8] = ov;
    }
    __syncthreads();

    int w = tid >> 5, lane = tid & 31;
    int wm = w & 3, wn = w >> 2;
    int lr = (lane & 7) + ((lane >> 3) & 1) * 8;
    int lc = (lane >> 4) * 8;
    uint32_t abase = smem_u32(As), bbase = smem_u32(Bs);

    float acc[8][4];
#pragma unroll
    for (int i = 0; i < 8; i++)
#pragma unroll
        for (int j = 0; j < 4; j++) acc[i][j] = 0.0f;

#pragma unroll
    for (int ks = 0; ks < 4; ks++) {
        int k0 = ks * 16;
        uint32_t a0, a1, a2, a3;
        LDMX4(a0, a1, a2, a3, abase + (uint32_t)(((wm * 16 + lr) * 72 + k0 + lc) * 2));
        uint32_t bb[8][2];
#pragma unroll
        for (int nt2 = 0; nt2 < 4; nt2++) {
            uint32_t r0, r1, r2, r3;
            LDMX4T(r0, r1, r2, r3,
                   bbase + (uint32_t)(((k0 + lr) * 136 + wn * 64 + nt2 * 16 + lc) * 2));
            bb[nt2 * 2][0] = r0;  bb[nt2 * 2][1] = r1;
            bb[nt2 * 2 + 1][0] = r2;  bb[nt2 * 2 + 1][1] = r3;
        }
#pragma unroll
        for (int nt = 0; nt < 8; nt++)
            MMA16816(acc[nt], a0, a1, a2, a3, bb[nt][0], bb[nt][1]);
    }

    // epilogue: store fp16 T2 (pre-BN2) + weighted stats
    int re = row0 + wm * 16 + (lane >> 2);
    int cb = wn * 64 + (lane & 3) * 2;
    float w0 = (re < n)     ? (float)g_count[re]     : 0.f;
    float w1 = (re + 8 < n) ? (float)g_count[re + 8] : 0.f;
#pragma unroll
    for (int nt = 0; nt < 8; nt++) {
        int c = cb + nt * 8;
        float bx = bias[c], by = bias[c + 1];
        float v0 = acc[nt][0] + bx, v1 = acc[nt][1] + by;
        float v2 = acc[nt][2] + bx, v3 = acc[nt][3] + by;
        if (re < n) {
            __half2 h = __floats2half2_rn(v0, v1);
            *(__half2*)&g_T2h[(size_t)re * COUT + c] = h;
        }
        if (re + 8 < n) {
            __half2 h = __floats2half2_rn(v2, v3);
            *(__half2*)&g_T2h[(size_t)(re + 8) * COUT + c] = h;
        }
        float s0 = w0 * v0 + w1 * v2, s1 = w0 * v1 + w1 * v3;
        float q0 = w0 * v0 * v0 + w1 * v2 * v2, q1 = w0 * v1 * v1 + w1 * v3 * v3;
#pragma unroll
        for (int m = 4; m < 32; m <<= 1) {
            s0 += __shfl_xor_sync(0xffffffffu, s0, m);
            s1 += __shfl_xor_sync(0xffffffffu, s1, m);
            q0 += __shfl_xor_sync(0xffffffffu, q0, m);
            q1 += __shfl_xor_sync(0xffffffffu, q1, m);
        }
        if (lane < 4) {
            int cl = (c & 63);    // column within this warp's 64-col half
            shs[w * 64 + cl] = s0;  shs[w * 64 + cl + 1] = s1;
            shq[w * 64 + cl] = q0;  shq[w * 64 + cl + 1] = q1;
        }
    }
    __syncthreads();
    if (tid < 128) {
        int wn_c = tid >> 6;        // which 64-col half
        int cl = tid & 63;
        double s = 0.0, q = 0.0;
#pragma unroll
        for (int u = 0; u < 4; u++) {
            int wi = wn_c * 4 + u;
            s += (double)shs[wi * 64 + cl];
            q += (double)shq[wi * 64 + cl];
        }
        int slot = blockIdx.x & (NSLOT - 1);
        atomicAdd(&g_sum2[slot * COUT + tid], s);
        atomicAdd(&g_sq2[slot * COUT + tid], q);
    }
}

// ---------------- K6: gather + bn2 affine + relu + max over k (fp16 table) -------
// One warp per output point. Lane l owns channels 4l..4l+3.
__global__ __launch_bounds__(256) void k_gather(const void* __restrict__ idxp,
                                                float* __restrict__ out, int n, int k) {
    int warp = (blockIdx.x * blockDim.x + threadIdx.x) >> 5;
    int lane = threadIdx.x & 31;
    if (warp >= n) return;
    int is64 = g_is64;

    float4 s2 = *(const float4*)&g_s2[lane * 4];
    float4 t2 = *(const float4*)&g_t2[lane * 4];
    float m0 = 0.f, m1 = 0.f, m2 = 0.f, m3 = 0.f;   // relu => result >= 0

    if (k == 16) {
        int r_mine = 0;
        if (lane < 16) {
            if (is64) r_mine = (int)((const long long*)idxp)[(size_t)warp * 16 + lane];
            else      r_mine = ((const int*)idxp)[(size_t)warp * 16 + lane];
        }
#pragma unroll
        for (int j = 0; j < 16; j++) {
            int r = __shfl_sync(0xffffffffu, r_mine, j);
            uint2 v = *(const uint2*)&g_T2h[(size_t)r * COUT + lane * 4];
            float2 f01 = __half22float2(*(__half2*)&v.x);
            float2 f23 = __half22float2(*(__half2*)&v.y);
            m0 = fmaxf(m0, fmaf(s2.x, f01.x, t2.x));
            m1 = fmaxf(m1, fmaf(s2.y, f01.y, t2.y));
            m2 = fmaxf(m2, fmaf(s2.z, f23.x, t2.z));
            m3 = fmaxf(m3, fmaf(s2.w, f23.y, t2.w));
        }
    } else {
        for (int j = 0; j < k; j++) {
            int r;
            if (is64) r = (int)((const long long*)idxp)[(size_t)warp * k + j];
            else      r = ((const int*)idxp)[(size_t)warp * k + j];
            uint2 v = *(const uint2*)&g_T2h[(size_t)r * COUT + lane * 4];
            float2 f01 = __half22float2(*(__half2*)&v.x);
            float2 f23 = __half22float2(*(__half2*)&v.y);
            m0 = fmaxf(m0, fmaf(s2.x, f01.x, t2.x));
            m1 = fmaxf(m1, fmaf(s2.y, f01.y, t2.y));
            m2 = fmaxf(m2, fmaf(s2.z, f23.x, t2.z));
            m3 = fmaxf(m3, fmaf(s2.w, f23.y, t2.w));
        }
    }
    *(float4*)&out[(size_t)warp * COUT + lane * 4] = make_float4(m0, m1, m2, m3);
}

// ---------------- host launcher ----------------
extern "C" void kernel_launch(void* const* d_in, const int* in_sizes, int n_in,
                              void* d_out, int out_size) {
    const float* feat = (const float*)d_in[0];
    const void*  idx  = d_in[1];
    const float* W1   = (const float*)d_in[2];
    const float* b1   = (const float*)d_in[3];
    const float* g1   = (const float*)d_in[4];
    const float* be1  = (const float*)d_in[5];
    const float* W2   = (const float*)d_in[6];
    const float* b2   = (const float*)d_in[7];
    const float* g2   = (const float*)d_in[8];
    const float* be2  = (const float*)d_in[9];
    float* out = (float*)d_out;

    int n  = in_sizes[0] / CIN;      // 100000
    int nk = in_sizes[1];            // n * k
    int k  = nk / n;                 // 16
    double M = (double)nk;

    k_zero<<<(n + 255) / 256, 256>>>(n);
    k_detect<<<1, 64>>>((const int*)idx, nk);
    k_hist<<<512, 256>>>(idx, nk);

    k_gemm1<<<(n + 127) / 128, 256>>>(feat, W1, b1, n);
    k_fin<CMID><<<1, CMID>>>(g1, be1, M);

    k_gemm2<<<(n + 63) / 64, 256>>>(W2, b2, n);
    k_fin<COUT><<<1, COUT>>>(g2, be2, M);

    k_gather<<<(n + 7) / 8, 256>>>(idx, out, n, k);
}

// round 9
// speedup vs baseline: 1.4505x; 1.0197x over previous
#include <cuda_runtime.h>
#include <cuda_fp16.h>
#include <cstdint>

#define N_MAX 100000
#define CIN   64
#define CMID  64
#define COUT  128
#define BN_EPS 1e-5
#define NSLOT 16

// ---------------- mma / ldmatrix helpers (sm_103a HMMA path) ----------------
__device__ __forceinline__ uint32_t smem_u32(const void* p) {
    return (uint32_t)__cvta_generic_to_shared(p);
}
#define LDMX4(r0, r1, r2, r3, addr) \
    asm volatile("ldmatrix.sync.aligned.m8n8.x4.shared.b16 {%0,%1,%2,%3}, [%4];" \
                 : "=r"(r0), "=r"(r1), "=r"(r2), "=r"(r3) : "r"(addr))
#define LDMX4T(r0, r1, r2, r3, addr) \
    asm volatile("ldmatrix.sync.aligned.m8n8.x4.trans.shared.b16 {%0,%1,%2,%3}, [%4];" \
                 : "=r"(r0), "=r"(r1), "=r"(r2), "=r"(r3) : "r"(addr))
#define MMA16816(d, a0, a1, a2, a3, b0, b1) \
    asm volatile("mma.sync.aligned.m16n8k16.row.col.f32.f16.f16.f32 " \
                 "{%0,%1,%2,%3}, {%4,%5,%6,%7}, {%8,%9}, {%0,%1,%2,%3};" \
                 : "+f"(d[0]), "+f"(d[1]), "+f"(d[2]), "+f"(d[3]) \
                 : "r"(a0), "r"(a1), "r"(a2), "r"(a3), "r"(b0), "r"(b1))

// ---------------- device scratch (static: no allocations allowed) ----------------
__device__ int    g_count[N_MAX];
__device__ __half g_T1h[(size_t)N_MAX * CMID];   // feat @ W1 + b1, fp16 (12.8 MB)
__device__ __half g_T2h[(size_t)N_MAX * COUT];   // T2 pre-BN2, fp16 (25.6 MB)
__device__ double g_sum1[NSLOT * CMID], g_sq1[NSLOT * CMID];
__device__ double g_sum2[NSLOT * COUT], g_sq2[NSLOT * COUT];
__device__ float  g_s1[CMID], g_t1[CMID];
__device__ float  g_s2[COUT], g_t2[COUT];
__device__ int    g_is64;

// ---------------- K0: zero counters + accumulators ----------------
__global__ void k_zero(int n) {
    int i  = blockIdx.x * blockDim.x + threadIdx.x;
    int st = gridDim.x * blockDim.x;
    for (int j = i; j < n; j += st) g_count[j] = 0;
    if (i < NSLOT * CMID) { g_sum1[i] = 0.0; g_sq1[i] = 0.0; }
    if (i < NSLOT * COUT) { g_sum2[i] = 0.0; g_sq2[i] = 0.0; }
}

// ---------------- K1a: detect idx dtype (int32 vs int64) ----------------
// idx in [0, n), n < 2^31. Little-endian int64 => every odd 32-bit word is 0.
__global__ void k_detect(const int* w, int nk) {
    __shared__ int ok;
    if (threadIdx.x == 0) ok = 1;
    __syncthreads();
    int m = 64;
    if (nk < 128) m = nk / 2;
    if ((int)threadIdx.x < m) {
        if (w[2 * threadIdx.x + 1] != 0) ok = 0;  // benign race: only writes 0
    }
    __syncthreads();
    if (threadIdx.x == 0) g_is64 = ok;
}

// ---------------- K1b: histogram of idx (vectorized int4 loads) ----------------
__global__ void k_hist(const void* idxp, int nk) {
    int is64 = g_is64;
    int i  = blockIdx.x * blockDim.x + threadIdx.x;
    int st = gridDim.x * blockDim.x;
    if ((nk & 3) == 0) {
        const int4* p = (const int4*)idxp;
        if (is64) {
            int nq = nk >> 1;      // int64: int4 = 2 entries {x=lo0, z=lo1}
            for (int e = i; e < nq; e += st) {
                int4 v = p[e];
                atomicAdd(&g_count[v.x], 1);
                atomicAdd(&g_count[v.z], 1);
            }
        } else {
            int nq = nk >> 2;
            for (int e = i; e < nq; e += st) {
                int4 v = p[e];
                atomicAdd(&g_count[v.x], 1);
                atomicAdd(&g_count[v.y], 1);
                atomicAdd(&g_count[v.z], 1);
                atomicAdd(&g_count[v.w], 1);
            }
        }
    } else {
        if (is64) {
            const long long* p = (const long long*)idxp;
            for (int e = i; e < nk; e += st) atomicAdd(&g_count[(int)p[e]], 1);
        } else {
            const int* p = (const int*)idxp;
            for (int e = i; e < nk; e += st) atomicAdd(&g_count[p[e]], 1);
        }
    }
}

// ---------------- K2: T1 = feat @ W1 + b1 via HMMA (256 rows/block) --------------
// 8 warps; warp w owns rows w*32..+31 as two sequential 16-row sub-tiles
// (accumulators reused). Fused W1 f32->f16 + weighted BN1 stats.
static const int SMEM1G = (256 * 72 + 64 * 72) * 2 + 64 * 4 + 2 * 8 * 64 * 4; // 50432B
__global__ __launch_bounds__(256) void k_gemm1(const float* __restrict__ feat,
                                               const float* __restrict__ W1,
                                               const float* __restrict__ b1, int n) {
    extern __shared__ __half smdyn[];
    __half* As = smdyn;                       // [256][72]
    __half* Bs = smdyn + 256 * 72;            // [64][72]
    float*  bias = (float*)(smdyn + 256 * 72 + 64 * 72);       // [64]
    float*  shs  = bias + 64;                  // [8][64]
    float*  shq  = shs + 8 * 64;               // [8][64]

    int tid = threadIdx.x;
    int row0 = blockIdx.x * 256;

    // Bs <- f16(W1)
    for (int t = tid; t < 64 * 16; t += 256) {
        int r = t >> 4, q = t & 15;
        float4 v = ((const float4*)W1)[r * 16 + q];
        __half2 h0 = __floats2half2_rn(v.x, v.y);
        __half2 h1 = __floats2half2_rn(v.z, v.w);
        uint2 pk; pk.x = *(uint32_t*)&h0; pk.y = *(uint32_t*)&h1;
        *(uint2*)&Bs[r * 72 + q * 4] = pk;
    }
    if (tid < 64) bias[tid] = b1[tid];
    // As <- f16(feat), 256 rows
    for (int t = tid; t < 256 * 16; t += 256) {
        int r = t >> 4, q = t & 15;
        int gr = row0 + r;
        float4 v = (gr < n) ? ((const float4*)feat)[(size_t)gr * 16 + q]
                            : make_float4(0.f, 0.f, 0.f, 0.f);
        __half2 h0 = __floats2half2_rn(v.x, v.y);
        __half2 h1 = __floats2half2_rn(v.z, v.w);
        uint2 pk; pk.x = *(uint32_t*)&h0; pk.y = *(uint32_t*)&h1;
        *(uint2*)&As[r * 72 + q * 4] = pk;
    }
    __syncthreads();

    int w = tid >> 5, lane = tid & 31;
    int lr = (lane & 7) + ((lane >> 3) & 1) * 8;
    int lc = (lane >> 4) * 8;
    uint32_t abase = smem_u32(As), bbase = smem_u32(Bs);
    int cb = (lane & 3) * 2;

#pragma unroll
    for (int sub = 0; sub < 2; sub++) {
        int rtile = w * 32 + sub * 16;
        float acc[8][4];
#pragma unroll
        for (int i = 0; i < 8; i++)
#pragma unroll
            for (int j = 0; j < 4; j++) acc[i][j] = 0.0f;

#pragma unroll
        for (int ks = 0; ks < 4; ks++) {
            int k0 = ks * 16;
            uint32_t a0, a1, a2, a3;
            LDMX4(a0, a1, a2, a3, abase + (uint32_t)(((rtile + lr) * 72 + k0 + lc) * 2));
            uint32_t bb[8][2];
#pragma unroll
            for (int nt2 = 0; nt2 < 4; nt2++) {
                uint32_t r0, r1, r2, r3;
                LDMX4T(r0, r1, r2, r3, bbase + (uint32_t)(((k0 + lr) * 72 + nt2 * 16 + lc) * 2));
                bb[nt2 * 2][0] = r0;  bb[nt2 * 2][1] = r1;
                bb[nt2 * 2 + 1][0] = r2;  bb[nt2 * 2 + 1][1] = r3;
            }
#pragma unroll
            for (int nt = 0; nt < 8; nt++)
                MMA16816(acc[nt], a0, a1, a2, a3, bb[nt][0], bb[nt][1]);
        }

        // epilogue for this sub-tile: store fp16 T1 + weighted stats
        int re = row0 + rtile + (lane >> 2);
        float w0 = (re < n)     ? (float)g_count[re]     : 0.f;
        float w1 = (re + 8 < n) ? (float)g_count[re + 8] : 0.f;
#pragma unroll
        for (int nt = 0; nt < 8; nt++) {
            int c = nt * 8 + cb;
            float bx = bias[c], by = bias[c + 1];
            float v0 = acc[nt][0] + bx, v1 = acc[nt][1] + by;
            float v2 = acc[nt][2] + bx, v3 = acc[nt][3] + by;
            if (re < n) {
                __half2 h = __floats2half2_rn(v0, v1);
                *(__half2*)&g_T1h[(size_t)re * CMID + c] = h;
            }
            if (re + 8 < n) {
                __half2 h = __floats2half2_rn(v2, v3);
                *(__half2*)&g_T1h[(size_t)(re + 8) * CMID + c] = h;
            }
            float s0 = w0 * v0 + w1 * v2, s1 = w0 * v1 + w1 * v3;
            float q0 = w0 * v0 * v0 + w1 * v2 * v2, q1 = w0 * v1 * v1 + w1 * v3 * v3;
#pragma unroll
            for (int m = 4; m < 32; m <<= 1) {
                s0 += __shfl_xor_sync(0xffffffffu, s0, m);
                s1 += __shfl_xor_sync(0xffffffffu, s1, m);
                q0 += __shfl_xor_sync(0xffffffffu, q0, m);
                q1 += __shfl_xor_sync(0xffffffffu, q1, m);
            }
            if (lane < 4) {
                if (sub == 0) {
                    shs[w * 64 + c] = s0;  shs[w * 64 + c + 1] = s1;
                    shq[w * 64 + c] = q0;  shq[w * 64 + c + 1] = q1;
                } else {
                    shs[w * 64 + c] += s0;  shs[w * 64 + c + 1] += s1;
                    shq[w * 64 + c] += q0;  shq[w * 64 + c + 1] += q1;
                }
            }
        }
    }
    __syncthreads();
    if (tid < 64) {
        double s = 0.0, q = 0.0;
#pragma unroll
        for (int u = 0; u < 8; u++) { s += (double)shs[u * 64 + tid]; q += (double)shq[u * 64 + tid]; }
        int slot = blockIdx.x & (NSLOT - 1);
        atomicAdd(&g_sum1[slot * CMID + tid], s);
        atomicAdd(&g_sq1[slot * CMID + tid], q);
    }
}

// ---------------- finalize BN affine: s = g*rsqrt(var+eps), t = be - mean*s ------
template <int C>
__global__ void k_fin(const float* __restrict__ g, const float* __restrict__ be, double M) {
    int c = threadIdx.x;
    if (c >= C) return;
    const double* S = (C == CMID) ? g_sum1 : g_sum2;
    const double* Q = (C == CMID) ? g_sq1  : g_sq2;
    float* so = (C == CMID) ? g_s1 : g_s2;
    float* to = (C == CMID) ? g_t1 : g_t2;
    double s = 0.0, q = 0.0;
#pragma unroll
    for (int u = 0; u < NSLOT; u++) { s += S[u * C + c]; q += Q[u * C + c]; }
    double mean = s / M;
    double var  = q / M - mean * mean;
    double rs   = 1.0 / sqrt(var + BN_EPS);
    float  sc   = (float)((double)g[c] * rs);
    so[c] = sc;
    to[c] = (float)((double)be[c] - mean * (double)sc);
}

// ---------------- K4: T2 = relu(bn1(T1)) @ W2 + b2 via HMMA (128 rows/block) -----
// 8 warps: wm = w&3 -> 16-row tile; wn = w>>2 -> 64-col half. Two sequential
// row sub-tiles (offset 0 / 64), accumulators reused. Fused BN1-affine + BN2 stats.
__global__ __launch_bounds__(256) void k_gemm2(const float* __restrict__ W2,
                                               const float* __restrict__ b2, int n) {
    __shared__ __half As[128 * 72];
    __shared__ __half Bs[64 * 136];
    __shared__ float  bias[128];
    __shared__ float  shs[8 * 64], shq[8 * 64];

    int tid = threadIdx.x;
    int row0 = blockIdx.x * 128;

    // Bs <- f16(W2); stride 136 halves (272B)
    for (int t = tid; t < 64 * 32; t += 256) {
        int r = t >> 5, q = t & 31;
        float4 v = ((const float4*)W2)[r * 32 + q];
        __half2 h0 = __floats2half2_rn(v.x, v.y);
        __half2 h1 = __floats2half2_rn(v.z, v.w);
        uint2 pk; pk.x = *(uint32_t*)&h0; pk.y = *(uint32_t*)&h1;
        *(uint2*)&Bs[r * 136 + q * 4] = pk;
    }
    if (tid < 128) bias[tid] = b2[tid];
    // As <- relu(bn1(T1h)) in fp16, 128 rows
    for (int t = tid; t < 128 * 8; t += 256) {
        int r = t >> 3, q = t & 7;
        int gr = row0 + r;
        uint4 hv = make_uint4(0u, 0u, 0u, 0u);
        if (gr < n) hv = *(const uint4*)&g_T1h[(size_t)gr * CMID + q * 8];
        uint32_t* hw = &hv.x;
        uint4 ov;
        uint32_t* ow = &ov.x;
#pragma unroll
        for (int j = 0; j < 4; j++) {
            int kc = q * 8 + j * 2;
            float2 f = __half22float2(*(__half2*)&hw[j]);
            f.x = fmaxf(fmaf(g_s1[kc],     f.x, g_t1[kc]),     0.0f);
            f.y = fmaxf(fmaf(g_s1[kc + 1], f.y, g_t1[kc + 1]), 0.0f);
            __half2 h = __floats2half2_rn(f.x, f.y);
            ow[j] = *(uint32_t*)&h;
        }
        *(uint4*)&As[r * 72 + q * 8] = ov;
    }
    __syncthreads();

    int w = tid >> 5, lane = tid & 31;
    int wm = w & 3, wn = w >> 2;
    int lr = (lane & 7) + ((lane >> 3) & 1) * 8;
    int lc = (lane >> 4) * 8;
    uint32_t abase = smem_u32(As), bbase = smem_u32(Bs);

#pragma unroll
    for (int sub = 0; sub < 2; sub++) {
        int rtile = wm * 16 + sub * 64;
        float acc[8][4];
#pragma unroll
        for (int i = 0; i < 8; i++)
#pragma unroll
            for (int j = 0; j < 4; j++) acc[i][j] = 0.0f;

#pragma unroll
        for (int ks = 0; ks < 4; ks++) {
            int k0 = ks * 16;
            uint32_t a0, a1, a2, a3;
            LDMX4(a0, a1, a2, a3, abase + (uint32_t)(((rtile + lr) * 72 + k0 + lc) * 2));
            uint32_t bb[8][2];
#pragma unroll
            for (int nt2 = 0; nt2 < 4; nt2++) {
                uint32_t r0, r1, r2, r3;
                LDMX4T(r0, r1, r2, r3,
                       bbase + (uint32_t)(((k0 + lr) * 136 + wn * 64 + nt2 * 16 + lc) * 2));
                bb[nt2 * 2][0] = r0;  bb[nt2 * 2][1] = r1;
                bb[nt2 * 2 + 1][0] = r2;  bb[nt2 * 2 + 1][1] = r3;
            }
#pragma unroll
            for (int nt = 0; nt < 8; nt++)
                MMA16816(acc[nt], a0, a1, a2, a3, bb[nt][0], bb[nt][1]);
        }

        // epilogue: store fp16 T2 (pre-BN2) + weighted stats
        int re = row0 + rtile + (lane >> 2);
        int cb = wn * 64 + (lane & 3) * 2;
        float w0 = (re < n)     ? (float)g_count[re]     : 0.f;
        float w1 = (re + 8 < n) ? (float)g_count[re + 8] : 0.f;
#pragma unroll
        for (int nt = 0; nt < 8; nt++) {
            int c = cb + nt * 8;
            float bx = bias[c], by = bias[c + 1];
            float v0 = acc[nt][0] + bx, v1 = acc[nt][1] + by;
            float v2 = acc[nt][2] + bx, v3 = acc[nt][3] + by;
            if (re < n) {
                __half2 h = __floats2half2_rn(v0, v1);
                *(__half2*)&g_T2h[(size_t)re * COUT + c] = h;
            }
            if (re + 8 < n) {
                __half2 h = __floats2half2_rn(v2, v3);
                *(__half2*)&g_T2h[(size_t)(re + 8) * COUT + c] = h;
            }
            float s0 = w0 * v0 + w1 * v2, s1 = w0 * v1 + w1 * v3;
            float q0 = w0 * v0 * v0 + w1 * v2 * v2, q1 = w0 * v1 * v1 + w1 * v3 * v3;
#pragma unroll
            for (int m = 4; m < 32; m <<= 1) {
                s0 += __shfl_xor_sync(0xffffffffu, s0, m);
                s1 += __shfl_xor_sync(0xffffffffu, s1, m);
                q0 += __shfl_xor_sync(0xffffffffu, q0, m);
                q1 += __shfl_xor_sync(0xffffffffu, q1, m);
            }
            if (lane < 4) {
                int cl = (c & 63);
                if (sub == 0) {
                    shs[w * 64 + cl] = s0;  shs[w * 64 + cl + 1] = s1;
                    shq[w * 64 + cl] = q0;  shq[w * 64 + cl + 1] = q1;
                } else {
                    shs[w * 64 + cl] += s0;  shs[w * 64 + cl + 1] += s1;
                    shq[w * 64 + cl] += q0;  shq[w * 64 + cl + 1] += q1;
                }
            }
        }
    }
    __syncthreads();
    if (tid < 128) {
        int wn_c = tid >> 6;
        int cl = tid & 63;
        double s = 0.0, q = 0.0;
#pragma unroll
        for (int u = 0; u < 4; u++) {
            int wi = wn_c * 4 + u;
            s += (double)shs[wi * 64 + cl];
            q += (double)shq[wi * 64 + cl];
        }
        int slot = blockIdx.x & (NSLOT - 1);
        atomicAdd(&g_sum2[slot * COUT + tid], s);
        atomicAdd(&g_sq2[slot * COUT + tid], q);
    }
}

// ---------------- K6: gather + bn2 affine + relu + max over k (fp16 table) -------
// One warp per output point. Lane l owns channels 4l..4l+3.
__global__ __launch_bounds__(256) void k_gather(const void* __restrict__ idxp,
                                                float* __restrict__ out, int n, int k) {
    int warp = (blockIdx.x * blockDim.x + threadIdx.x) >> 5;
    int lane = threadIdx.x & 31;
    if (warp >= n) return;
    int is64 = g_is64;

    float4 s2 = *(const float4*)&g_s2[lane * 4];
    float4 t2 = *(const float4*)&g_t2[lane * 4];
    float m0 = 0.f, m1 = 0.f, m2 = 0.f, m3 = 0.f;   // relu => result >= 0

    if (k == 16) {
        int r_mine = 0;
        if (lane < 16) {
            if (is64) r_mine = (int)((const long long*)idxp)[(size_t)warp * 16 + lane];
            else      r_mine = ((const int*)idxp)[(size_t)warp * 16 + lane];
        }
#pragma unroll
        for (int j = 0; j < 16; j++) {
            int r = __shfl_sync(0xffffffffu, r_mine, j);
            uint2 v = *(const uint2*)&g_T2h[(size_t)r * COUT + lane * 4];
            float2 f01 = __half22float2(*(__half2*)&v.x);
            float2 f23 = __half22float2(*(__half2*)&v.y);
            m0 = fmaxf(m0, fmaf(s2.x, f01.x, t2.x));
            m1 = fmaxf(m1, fmaf(s2.y, f01.y, t2.y));
            m2 = fmaxf(m2, fmaf(s2.z, f23.x, t2.z));
            m3 = fmaxf(m3, fmaf(s2.w, f23.y, t2.w));
        }
    } else {
        for (int j = 0; j < k; j++) {
            int r;
            if (is64) r = (int)((const long long*)idxp)[(size_t)warp * k + j];
            else      r = ((const int*)idxp)[(size_t)warp * k + j];
            uint2 v = *(const uint2*)&g_T2h[(size_t)r * COUT + lane * 4];
            float2 f01 = __half22float2(*(__half2*)&v.x);
            float2 f23 = __half22float2(*(__half2*)&v.y);
            m0 = fmaxf(m0, fmaf(s2.x, f01.x, t2.x));
            m1 = fmaxf(m1, fmaf(s2.y, f01.y, t2.y));
            m2 = fmaxf(m2, fmaf(s2.z, f23.x, t2.z));
            m3 = fmaxf(m3, fmaf(s2.w, f23.y, t2.w));
        }
    }
    *(float4*)&out[(size_t)warp * COUT + lane * 4] = make_float4(m0, m1, m2, m3);
}

// ---------------- host launcher ----------------
extern "C" void kernel_launch(void* const* d_in, const int* in_sizes, int n_in,
                              void* d_out, int out_size) {
    const float* feat = (const float*)d_in[0];
    const void*  idx  = d_in[1];
    const float* W1   = (const float*)d_in[2];
    const float* b1   = (const float*)d_in[3];
    const float* g1   = (const float*)d_in[4];
    const float* be1  = (const float*)d_in[5];
    const float* W2   = (const float*)d_in[6];
    const float* b2   = (const float*)d_in[7];
    const float* g2   = (const float*)d_in[8];
    const float* be2  = (const float*)d_in[9];
    float* out = (float*)d_out;

    int n  = in_sizes[0] / CIN;      // 100000
    int nk = in_sizes[1];            // n * k
    int k  = nk / n;                 // 16
    double M = (double)nk;

    cudaFuncSetAttribute(k_gemm1, cudaFuncAttributeMaxDynamicSharedMemorySize, SMEM1G);

    k_zero<<<(n + 255) / 256, 256>>>(n);
    k_detect<<<1, 64>>>((const int*)idx, nk);
    k_hist<<<512, 256>>>(idx, nk);

    k_gemm1<<<(n + 255) / 256, 256, SMEM1G>>>(feat, W1, b1, n);
    k_fin<CMID><<<1, CMID>>>(g1, be1, M);

    k_gemm2<<<(n + 127) / 128, 256>>>(W2, b2, n);
    k_fin<COUT><<<1, COUT>>>(g2, be2, M);

    k_gather<<<(n + 7) / 8, 256>>>(idx, out, n, k);
}

// round 10
// speedup vs baseline: 1.4762x; 1.0178x over previous
#include <cuda_runtime.h>
#include <cuda_fp16.h>
#include <cstdint>

#define N_MAX 100000
#define CIN   64
#define CMID  64
#define COUT  128
#define BN_EPS 1e-5
#define NSLOT 16

// ---------------- mma / ldmatrix helpers (sm_103a HMMA path) ----------------
__device__ __forceinline__ uint32_t smem_u32(const void* p) {
    return (uint32_t)__cvta_generic_to_shared(p);
}
#define LDMX4T(r0, r1, r2, r3, addr) \
    asm volatile("ldmatrix.sync.aligned.m8n8.x4.trans.shared.b16 {%0,%1,%2,%3}, [%4];" \
                 : "=r"(r0), "=r"(r1), "=r"(r2), "=r"(r3) : "r"(addr))
#define MMA16816(d, a0, a1, a2, a3, b0, b1) \
    asm volatile("mma.sync.aligned.m16n8k16.row.col.f32.f16.f16.f32 " \
                 "{%0,%1,%2,%3}, {%4,%5,%6,%7}, {%8,%9}, {%0,%1,%2,%3};" \
                 : "+f"(d[0]), "+f"(d[1]), "+f"(d[2]), "+f"(d[3]) \
                 : "r"(a0), "r"(a1), "r"(a2), "r"(a3), "r"(b0), "r"(b1))

// ---------------- device scratch (static: no allocations allowed) ----------------
__device__ int    g_count[N_MAX];
__device__ __half g_T1h[(size_t)N_MAX * CMID];   // feat @ W1 + b1, fp16 (12.8 MB)
__device__ __half g_T2h[(size_t)N_MAX * COUT];   // T2 pre-BN2, fp16 (25.6 MB)
__device__ double g_sum1[NSLOT * CMID], g_sq1[NSLOT * CMID];
__device__ double g_sum2[NSLOT * COUT], g_sq2[NSLOT * COUT];
__device__ float  g_s1[CMID], g_t1[CMID];
__device__ float  g_s2[COUT], g_t2[COUT];
__device__ int    g_is64;

// ---------------- K0: zero counters/accumulators + detect idx dtype -------------
// idx in [0, n), n < 2^31. Little-endian int64 => every odd 32-bit word is 0.
__global__ void k_init(const int* w, int nk, int n) {
    int i  = blockIdx.x * blockDim.x + threadIdx.x;
    int st = gridDim.x * blockDim.x;
    for (int j = i; j < n; j += st) g_count[j] = 0;
    if (i < NSLOT * CMID) { g_sum1[i] = 0.0; g_sq1[i] = 0.0; }
    if (i < NSLOT * COUT) { g_sum2[i] = 0.0; g_sq2[i] = 0.0; }
    if (blockIdx.x == 0) {
        __shared__ int ok;
        if (threadIdx.x == 0) ok = 1;
        __syncthreads();
        int m = 64;
        if (nk < 128) m = nk / 2;
        if ((int)threadIdx.x < m) {
            if (w[2 * threadIdx.x + 1] != 0) ok = 0;  // benign race: only writes 0
        }
        __syncthreads();
        if (threadIdx.x == 0) g_is64 = ok;
    }
}

// ---------------- K1: histogram of idx (vectorized int4 loads) ----------------
__global__ void k_hist(const void* idxp, int nk) {
    int is64 = g_is64;
    int i  = blockIdx.x * blockDim.x + threadIdx.x;
    int st = gridDim.x * blockDim.x;
    if ((nk & 3) == 0) {
        const int4* p = (const int4*)idxp;
        if (is64) {
            int nq = nk >> 1;      // int64: int4 = 2 entries {x=lo0, z=lo1}
            for (int e = i; e < nq; e += st) {
                int4 v = p[e];
                atomicAdd(&g_count[v.x], 1);
                atomicAdd(&g_count[v.z], 1);
            }
        } else {
            int nq = nk >> 2;
            for (int e = i; e < nq; e += st) {
                int4 v = p[e];
                atomicAdd(&g_count[v.x], 1);
                atomicAdd(&g_count[v.y], 1);
                atomicAdd(&g_count[v.z], 1);
                atomicAdd(&g_count[v.w], 1);
            }
        }
    } else {
        if (is64) {
            const long long* p = (const long long*)idxp;
            for (int e = i; e < nk; e += st) atomicAdd(&g_count[(int)p[e]], 1);
        } else {
            const int* p = (const int*)idxp;
            for (int e = i; e < nk; e += st) atomicAdd(&g_count[p[e]], 1);
        }
    }
}

// ---------------- K2: T1 = feat @ W1 + b1 via HMMA, A-frags direct from GMEM ----
// 128 rows/block, 8 warps, warp w owns rows w*16..+15. No A smem staging.
__global__ __launch_bounds__(256, 3) void k_gemm1(const float* __restrict__ feat,
                                                  const float* __restrict__ W1,
                                                  const float* __restrict__ b1, int n) {
    __shared__ __half Bs[64 * 72];
    __shared__ float  bias[64];
    __shared__ float  shs[8 * 64], shq[8 * 64];

    int tid = threadIdx.x;
    // Bs <- f16(W1)
    for (int t = tid; t < 64 * 16; t += 256) {
        int r = t >> 4, q = t & 15;
        float4 v = ((const float4*)W1)[t];
        __half2 h0 = __floats2half2_rn(v.x, v.y);
        __half2 h1 = __floats2half2_rn(v.z, v.w);
        uint2 pk; pk.x = *(uint32_t*)&h0; pk.y = *(uint32_t*)&h1;
        *(uint2*)&Bs[r * 72 + q * 4] = pk;
    }
    if (tid < 64) bias[tid] = b1[tid];
    __syncthreads();

    int w = tid >> 5, lane = tid & 31;
    int rq = lane >> 2, cq = lane & 3;
    int rt = blockIdx.x * 128 + w * 16;
    int lr = (lane & 7) + ((lane >> 3) & 1) * 8;
    int lc = (lane >> 4) * 8;
    uint32_t bbase = smem_u32(Bs);

    int r0 = rt + rq, r1 = rt + rq + 8;
    bool v0 = r0 < n, v1 = r1 < n;
    const float2* f0 = (const float2*)(feat + (size_t)(v0 ? r0 : 0) * CIN);
    const float2* f1 = (const float2*)(feat + (size_t)(v1 ? r1 : 0) * CIN);
    const float2 z2 = make_float2(0.f, 0.f);

    float acc[8][4];
#pragma unroll
    for (int i = 0; i < 8; i++)
#pragma unroll
        for (int j = 0; j < 4; j++) acc[i][j] = 0.0f;

    // buf[.][f]: f0=(r0,klo) f1=(r1,klo) f2=(r0,khi) f3=(r1,khi)
    float2 buf[2][4];
    {
        int cidx = cq;           // float2 index = (kc*16 + 2cq)/2 with kc=0
        buf[0][0] = v0 ? f0[cidx]     : z2;
        buf[0][1] = v1 ? f1[cidx]     : z2;
        buf[0][2] = v0 ? f0[cidx + 4] : z2;
        buf[0][3] = v1 ? f1[cidx + 4] : z2;
    }
#pragma unroll
    for (int kc = 0; kc < 4; kc++) {
        if (kc < 3) {
            int cidx = (kc + 1) * 8 + cq;
            float2* d = buf[(kc + 1) & 1];
            d[0] = v0 ? f0[cidx]     : z2;
            d[1] = v1 ? f1[cidx]     : z2;
            d[2] = v0 ? f0[cidx + 4] : z2;
            d[3] = v1 ? f1[cidx + 4] : z2;
        }
        uint32_t A[4];
#pragma unroll
        for (int f = 0; f < 4; f++) {
            __half2 h = __floats2half2_rn(buf[kc & 1][f].x, buf[kc & 1][f].y);
            A[f] = *(uint32_t*)&h;
        }
        int k0 = kc * 16;
#pragma unroll
        for (int nt2 = 0; nt2 < 4; nt2++) {
            uint32_t b0, b1v, b2, b3;
            LDMX4T(b0, b1v, b2, b3, bbase + (uint32_t)(((k0 + lr) * 72 + nt2 * 16 + lc) * 2));
            MMA16816(acc[nt2 * 2],     A[0], A[1], A[2], A[3], b0, b1v);
            MMA16816(acc[nt2 * 2 + 1], A[0], A[1], A[2], A[3], b2, b3);
        }
    }

    // epilogue: store fp16 T1 + weighted stats
    float w0 = v0 ? (float)g_count[r0] : 0.f;
    float w1 = v1 ? (float)g_count[r1] : 0.f;
    int cb = cq * 2;
#pragma unroll
    for (int nt = 0; nt < 8; nt++) {
        int c = nt * 8 + cb;
        float bx = bias[c], by = bias[c + 1];
        float x0 = acc[nt][0] + bx, x1 = acc[nt][1] + by;
        float x2 = acc[nt][2] + bx, x3 = acc[nt][3] + by;
        if (v0) {
            __half2 h = __floats2half2_rn(x0, x1);
            *(__half2*)&g_T1h[(size_t)r0 * CMID + c] = h;
        }
        if (v1) {
            __half2 h = __floats2half2_rn(x2, x3);
            *(__half2*)&g_T1h[(size_t)r1 * CMID + c] = h;
        }
        float s0 = w0 * x0 + w1 * x2, s1 = w0 * x1 + w1 * x3;
        float q0 = w0 * x0 * x0 + w1 * x2 * x2, q1 = w0 * x1 * x1 + w1 * x3 * x3;
#pragma unroll
        for (int m = 4; m < 32; m <<= 1) {
            s0 += __shfl_xor_sync(0xffffffffu, s0, m);
            s1 += __shfl_xor_sync(0xffffffffu, s1, m);
            q0 += __shfl_xor_sync(0xffffffffu, q0, m);
            q1 += __shfl_xor_sync(0xffffffffu, q1, m);
        }
        if (lane < 4) {
            shs[w * 64 + c] = s0;  shs[w * 64 + c + 1] = s1;
            shq[w * 64 + c] = q0;  shq[w * 64 + c + 1] = q1;
        }
    }
    __syncthreads();
    if (tid < 64) {
        double s = 0.0, q = 0.0;
#pragma unroll
        for (int u = 0; u < 8; u++) { s += (double)shs[u * 64 + tid]; q += (double)shq[u * 64 + tid]; }
        int slot = blockIdx.x & (NSLOT - 1);
        atomicAdd(&g_sum1[slot * CMID + tid], s);
        atomicAdd(&g_sq1[slot * CMID + tid], q);
    }
}

// ---------------- finalize BN affine: s = g*rsqrt(var+eps), t = be - mean*s ------
template <int C>
__global__ void k_fin(const float* __restrict__ g, const float* __restrict__ be, double M) {
    int c = threadIdx.x;
    if (c >= C) return;
    const double* S = (C == CMID) ? g_sum1 : g_sum2;
    const double* Q = (C == CMID) ? g_sq1  : g_sq2;
    float* so = (C == CMID) ? g_s1 : g_s2;
    float* to = (C == CMID) ? g_t1 : g_t2;
    double s = 0.0, q = 0.0;
#pragma unroll
    for (int u = 0; u < NSLOT; u++) { s += S[u * C + c]; q += Q[u * C + c]; }
    double mean = s / M;
    double var  = q / M - mean * mean;
    double rs   = 1.0 / sqrt(var + BN_EPS);
    float  sc   = (float)((double)g[c] * rs);
    so[c] = sc;
    to[c] = (float)((double)be[c] - mean * (double)sc);
}

// ---------------- K4: T2 = relu(bn1(T1)) @ W2 + b2 via HMMA, A-frags from GMEM ---
// 128 rows/block, 8 warps, warp w owns rows w*16..+15, loops 2 col-halves.
// BN1 affine+relu applied in registers on loaded T1h fragments.
__global__ __launch_bounds__(256, 3) void k_gemm2(const float* __restrict__ W2,
                                                  const float* __restrict__ b2, int n) {
    __shared__ __half Bs[64 * 136];
    __shared__ float  bias[128];
    __shared__ float  s1s[64], t1s[64];
    __shared__ float  shs[8 * 128], shq[8 * 128];

    int tid = threadIdx.x;
    // Bs <- f16(W2); stride 136 halves (272B)
    for (int t = tid; t < 64 * 32; t += 256) {
        int r = t >> 5, q = t & 31;
        float4 v = ((const float4*)W2)[t];
        __half2 h0 = __floats2half2_rn(v.x, v.y);
        __half2 h1 = __floats2half2_rn(v.z, v.w);
        uint2 pk; pk.x = *(uint32_t*)&h0; pk.y = *(uint32_t*)&h1;
        *(uint2*)&Bs[r * 136 + q * 4] = pk;
    }
    if (tid < 128) bias[tid] = b2[tid];
    if (tid < 64) { s1s[tid] = g_s1[tid]; t1s[tid] = g_t1[tid]; }
    __syncthreads();

    int w = tid >> 5, lane = tid & 31;
    int rq = lane >> 2, cq = lane & 3;
    int rt = blockIdx.x * 128 + w * 16;
    int lr = (lane & 7) + ((lane >> 3) & 1) * 8;
    int lc = (lane >> 4) * 8;
    uint32_t bbase = smem_u32(Bs);

    int r0 = rt + rq, r1 = rt + rq + 8;
    bool v0 = r0 < n, v1 = r1 < n;
    const uint32_t* t0 = (const uint32_t*)(g_T1h + (size_t)(v0 ? r0 : 0) * CMID);
    const uint32_t* t1p = (const uint32_t*)(g_T1h + (size_t)(v1 ? r1 : 0) * CMID);

    // Build all A fragments (relu(bn1(T1))) once: af[kc][f], 16 regs
    uint32_t af[4][4];
#pragma unroll
    for (int kc = 0; kc < 4; kc++) {
#pragma unroll
        for (int f = 0; f < 4; f++) {
            int col = kc * 16 + ((f >> 1) << 3) + 2 * cq;
            bool vv = (f & 1) ? v1 : v0;
            uint32_t raw = vv ? ((f & 1) ? t1p[col >> 1] : t0[col >> 1]) : 0u;
            float2 fv = __half22float2(*(__half2*)&raw);
            float2 s = *(const float2*)&s1s[col];
            float2 t = *(const float2*)&t1s[col];
            fv.x = fmaxf(fmaf(s.x, fv.x, t.x), 0.0f);
            fv.y = fmaxf(fmaf(s.y, fv.y, t.y), 0.0f);
            __half2 h = __floats2half2_rn(fv.x, fv.y);
            af[kc][f] = *(uint32_t*)&h;
        }
    }

    float w0 = v0 ? (float)g_count[r0] : 0.f;
    float w1 = v1 ? (float)g_count[r1] : 0.f;
    int cbq = cq * 2;

#pragma unroll
    for (int half = 0; half < 2; half++) {
        float acc[8][4];
#pragma unroll
        for (int i = 0; i < 8; i++)
#pragma unroll
            for (int j = 0; j < 4; j++) acc[i][j] = 0.0f;

#pragma unroll
        for (int kc = 0; kc < 4; kc++) {
            int k0 = kc * 16;
#pragma unroll
            for (int nt2 = 0; nt2 < 4; nt2++) {
                uint32_t b0, b1v, b2, b3;
                LDMX4T(b0, b1v, b2, b3,
                       bbase + (uint32_t)(((k0 + lr) * 136 + half * 64 + nt2 * 16 + lc) * 2));
                MMA16816(acc[nt2 * 2],     af[kc][0], af[kc][1], af[kc][2], af[kc][3], b0, b1v);
                MMA16816(acc[nt2 * 2 + 1], af[kc][0], af[kc][1], af[kc][2], af[kc][3], b2, b3);
            }
        }

        // epilogue: store fp16 T2 (pre-BN2) + weighted stats
#pragma unroll
        for (int nt = 0; nt < 8; nt++) {
            int c = half * 64 + nt * 8 + cbq;
            float bx = bias[c], by = bias[c + 1];
            float x0 = acc[nt][0] + bx, x1 = acc[nt][1] + by;
            float x2 = acc[nt][2] + bx, x3 = acc[nt][3] + by;
            if (v0) {
                __half2 h = __floats2half2_rn(x0, x1);
                *(__half2*)&g_T2h[(size_t)r0 * COUT + c] = h;
            }
            if (v1) {
                __half2 h = __floats2half2_rn(x2, x3);
                *(__half2*)&g_T2h[(size_t)r1 * COUT + c] = h;
            }
            float s0 = w0 * x0 + w1 * x2, s1 = w0 * x1 + w1 * x3;
            float q0 = w0 * x0 * x0 + w1 * x2 * x2, q1 = w0 * x1 * x1 + w1 * x3 * x3;
#pragma unroll
            for (int m = 4; m < 32; m <<= 1) {
                s0 += __shfl_xor_sync(0xffffffffu, s0, m);
                s1 += __shfl_xor_sync(0xffffffffu, s1, m);
                q0 += __shfl_xor_sync(0xffffffffu, q0, m);
                q1 += __shfl_xor_sync(0xffffffffu, q1, m);
            }
            if (lane < 4) {
                shs[w * 128 + c] = s0;  shs[w * 128 + c + 1] = s1;
                shq[w * 128 + c] = q0;  shq[w * 128 + c + 1] = q1;
            }
        }
    }
    __syncthreads();
    if (tid < 128) {
        double s = 0.0, q = 0.0;
#pragma unroll
        for (int u = 0; u < 8; u++) { s += (double)shs[u * 128 + tid]; q += (double)shq[u * 128 + tid]; }
        int slot = blockIdx.x & (NSLOT - 1);
        atomicAdd(&g_sum2[slot * COUT + tid], s);
        atomicAdd(&g_sq2[slot * COUT + tid], q);
    }
}

// ---------------- K6: gather + bn2 affine + relu + max over k (fp16 table) -------
// One warp per output point. Lane l owns channels 4l..4l+3.
__global__ __launch_bounds__(256) void k_gather(const void* __restrict__ idxp,
                                                float* __restrict__ out, int n, int k) {
    int warp = (blockIdx.x * blockDim.x + threadIdx.x) >> 5;
    int lane = threadIdx.x & 31;
    if (warp >= n) return;
    int is64 = g_is64;

    float4 s2 = *(const float4*)&g_s2[lane * 4];
    float4 t2 = *(const float4*)&g_t2[lane * 4];
    float m0 = 0.f, m1 = 0.f, m2 = 0.f, m3 = 0.f;   // relu => result >= 0

    if (k == 16) {
        int r_mine = 0;
        if (lane < 16) {
            if (is64) r_mine = (int)((const long long*)idxp)[(size_t)warp * 16 + lane];
            else      r_mine = ((const int*)idxp)[(size_t)warp * 16 + lane];
        }
#pragma unroll
        for (int j = 0; j < 16; j++) {
            int r = __shfl_sync(0xffffffffu, r_mine, j);
            uint2 v = *(const uint2*)&g_T2h[(size_t)r * COUT + lane * 4];
            float2 f01 = __half22float2(*(__half2*)&v.x);
            float2 f23 = __half22float2(*(__half2*)&v.y);
            m0 = fmaxf(m0, fmaf(s2.x, f01.x, t2.x));
            m1 = fmaxf(m1, fmaf(s2.y, f01.y, t2.y));
            m2 = fmaxf(m2, fmaf(s2.z, f23.x, t2.z));
            m3 = fmaxf(m3, fmaf(s2.w, f23.y, t2.w));
        }
    } else {
        for (int j = 0; j < k; j++) {
            int r;
            if (is64) r = (int)((const long long*)idxp)[(size_t)warp * k + j];
            else      r = ((const int*)idxp)[(size_t)warp * k + j];
            uint2 v = *(const uint2*)&g_T2h[(size_t)r * COUT + lane * 4];
            float2 f01 = __half22float2(*(__half2*)&v.x);
            float2 f23 = __half22float2(*(__half2*)&v.y);
            m0 = fmaxf(m0, fmaf(s2.x, f01.x, t2.x));
            m1 = fmaxf(m1, fmaf(s2.y, f01.y, t2.y));
            m2 = fmaxf(m2, fmaf(s2.z, f23.x, t2.z));
            m3 = fmaxf(m3, fmaf(s2.w, f23.y, t2.w));
        }
    }
    *(float4*)&out[(size_t)warp * COUT + lane * 4] = make_float4(m0, m1, m2, m3);
}

// ---------------- host launcher ----------------
extern "C" void kernel_launch(void* const* d_in, const int* in_sizes, int n_in,
                              void* d_out, int out_size) {
    const float* feat = (const float*)d_in[0];
    const void*  idx  = d_in[1];
    const float* W1   = (const float*)d_in[2];
    const float* b1   = (const float*)d_in[3];
    const float* g1   = (const float*)d_in[4];
    const float* be1  = (const float*)d_in[5];
    const float* W2   = (const float*)d_in[6];
    const float* b2   = (const float*)d_in[7];
    const float* g2   = (const float*)d_in[8];
    const float* be2  = (const float*)d_in[9];
    float* out = (float*)d_out;

    int n  = in_sizes[0] / CIN;      // 100000
    int nk = in_sizes[1];            // n * k
    int k  = nk / n;                 // 16
    double M = (double)nk;

    k_init<<<(n + 255) / 256, 256>>>((const int*)idx, nk, n);
    k_hist<<<512, 256>>>(idx, nk);

    k_gemm1<<<(n + 127) / 128, 256>>>(feat, W1, b1, n);
    k_fin<CMID><<<1, CMID>>>(g1, be1, M);

    k_gemm2<<<(n + 127) / 128, 256>>>(W2, b2, n);
    k_fin<COUT><<<1, COUT>>>(g2, be2, M);

    k_gather<<<(n + 7) / 8, 256>>>(idx, out, n, k);
}